// round 5
// baseline (speedup 1.0000x reference)
#include <cuda_runtime.h>
#include <cuda_bf16.h>
#include <cstdint>

#define NN 50000
#define EE 1600000

typedef __nv_bfloat16 bf16;
typedef __nv_bfloat162 bf162;

// ---------------- device scratch (no allocs allowed) ----------------
__device__ __align__(256) bf16 g_ain_hi[NN * 512];
__device__ __align__(256) bf16 g_ain_lo[NN * 512];
__device__ __align__(256) bf16 g_t_hi[NN * 128];
__device__ __align__(256) bf16 g_t_lo[NN * 128];
__device__ __align__(256) bf16 g_h_hi[NN * 128];
__device__ __align__(256) bf16 g_h_lo[NN * 128];
__device__ __align__(256) bf16 g_cat_hi[NN * 512];
__device__ __align__(256) bf16 g_cat_lo[NN * 512];
__device__ __align__(256) float g_comb[NN * 128];
__device__ __align__(256) bf16 g_w_hi[1536 * 128];
__device__ __align__(256) bf16 g_w_lo[1536 * 128];
__device__ int   g_cnt[NN];
__device__ float g_dinv[NN];
__device__ int   g_rowptr[NN + 1];
__device__ int   g_cur[NN];
__device__ int   g_srcidx[EE];
__device__ int   g_is64;

// ---------------- helpers ----------------
__device__ __forceinline__ uint32_t smem_to_u32(const void* p) {
    uint32_t a;
    asm("{ .reg .u64 t; cvta.to.shared.u64 t, %1; cvt.u32.u64 %0, t; }" : "=r"(a) : "l"(p));
    return a;
}
__device__ __forceinline__ void cpa16(uint32_t d, const void* s, int sz) {
    asm volatile("cp.async.cg.shared.global [%0], [%1], 16, %2;"
                 :: "r"(d), "l"(s), "r"(sz) : "memory");
}
#define CP_COMMIT() asm volatile("cp.async.commit_group;" ::: "memory")
#define CP_WAIT1()  asm volatile("cp.async.wait_group 1;" ::: "memory")
#define CP_WAIT0()  asm volatile("cp.async.wait_group 0;" ::: "memory")

#define LDSM_X4(d, a) \
    asm volatile("ldmatrix.sync.aligned.m8n8.x4.shared.b16 {%0,%1,%2,%3}, [%4];" \
        : "=r"((d)[0]), "=r"((d)[1]), "=r"((d)[2]), "=r"((d)[3]) : "r"(a))
#define LDSM_X4_T(d, a) \
    asm volatile("ldmatrix.sync.aligned.m8n8.x4.trans.shared.b16 {%0,%1,%2,%3}, [%4];" \
        : "=r"((d)[0]), "=r"((d)[1]), "=r"((d)[2]), "=r"((d)[3]) : "r"(a))
#define MMA_BF16(c, a, b0, b1) \
    asm volatile("mma.sync.aligned.m16n8k16.row.col.f32.bf16.bf16.f32 " \
        "{%0,%1,%2,%3}, {%4,%5,%6,%7}, {%8,%9}, {%0,%1,%2,%3};" \
        : "+f"((c)[0]), "+f"((c)[1]), "+f"((c)[2]), "+f"((c)[3]) \
        : "r"((a)[0]), "r"((a)[1]), "r"((a)[2]), "r"((a)[3]), "r"(b0), "r"(b1))

// per-stage smem: A_hi 128x(32+8pad)bf16=10240B | A_lo 10240 | B_hi 32x(128+8)bf16=8704 | B_lo 8704
#define BUFS    37888
#define OFF_ALO 10240
#define OFF_BHI 20480
#define OFF_BLO 29184
#define NSTAGE  3
#define SMEM_DYN (NSTAGE * BUFS)

// ---------------- HMMA split-bf16 plane GEMM: C[M,128] = A[M,K] @ W[K,128] ----------------
template <int ACT, int OUTF>   // OUTF: 0 = f32 Cf, 1 = bf16 hi/lo planes
__global__ __launch_bounds__(512) void pgemm(
    const bf16* __restrict__ Ahi, const bf16* __restrict__ Alo, int lda,
    const bf16* __restrict__ Whi, const bf16* __restrict__ Wlo,
    const float* __restrict__ bias,
    float* __restrict__ Cf, bf16* __restrict__ Chi, bf16* __restrict__ Clo,
    int ldc, int M, int K)
{
    extern __shared__ char smem[];
    const uint32_t sb = smem_to_u32(smem);
    const int tid = threadIdx.x, wid = tid >> 5, lane = tid & 31;
    const int m0 = blockIdx.x * 128;
    const int m_off = (wid & 3) * 32, n_off = (wid >> 2) * 32;

    // ldmatrix lane address components
    const int mi = lane >> 3, r8 = lane & 7;
    const int aRowL = m_off + (mi & 1) * 8 + r8;
    const int aColL = (mi >> 1) * 8;
    const int bRowL = (mi & 1) * 8 + r8;
    const int bColL = n_off + (mi >> 1) * 8;

    // cp.async mapping
    const int arow = tid >> 2, aq = tid & 3;          // A: 128 rows x 4 x 16B
    const int brow = tid >> 4, bq = tid & 15;         // B: 32 rows x 16 x 16B
    const int aValid = (m0 + arow < M) ? 16 : 0;

    float acc[2][4][4];
#pragma unroll
    for (int mt = 0; mt < 2; mt++)
#pragma unroll
        for (int nt = 0; nt < 4; nt++)
#pragma unroll
            for (int j = 0; j < 4; j++) acc[mt][nt][j] = 0.f;

    const int nch = K >> 5;

    auto issue = [&](int c, int slot) {
        const uint32_t base = sb + slot * BUFS;
        const size_t aoff = (size_t)(m0 + arow) * lda + c * 32 + aq * 8;
        cpa16(base + arow * 80 + aq * 16, Ahi + aoff, aValid);
        cpa16(base + OFF_ALO + arow * 80 + aq * 16, Alo + aoff, aValid);
        const size_t boff = (size_t)(c * 32 + brow) * 128 + bq * 8;
        cpa16(base + OFF_BHI + brow * 272 + bq * 16, Whi + boff, 16);
        cpa16(base + OFF_BLO + brow * 272 + bq * 16, Wlo + boff, 16);
    };
    auto compute = [&](int slot) {
        const uint32_t aH = sb + slot * BUFS;
        const uint32_t aL = aH + OFF_ALO;
        const uint32_t bH = aH + OFF_BHI;
#pragma unroll
        for (int k16 = 0; k16 < 2; k16++) {
            uint32_t ah[2][4], bh[2][4], bl[2][4];
#pragma unroll
            for (int mt = 0; mt < 2; mt++)
                LDSM_X4(ah[mt], aH + (uint32_t)(((aRowL + mt * 16) * 40 + aColL + k16 * 16) * 2));
#pragma unroll
            for (int nt = 0; nt < 2; nt++) {
                const uint32_t ba = bH +
                    (uint32_t)(((bRowL + k16 * 16) * 136 + bColL + nt * 16) * 2);
                LDSM_X4_T(bh[nt], ba);
                LDSM_X4_T(bl[nt], ba + (OFF_BLO - OFF_BHI));
            }
#pragma unroll
            for (int mt = 0; mt < 2; mt++)
#pragma unroll
                for (int nt = 0; nt < 2; nt++) {
                    MMA_BF16(acc[mt][nt * 2 + 0], ah[mt], bh[nt][0], bh[nt][1]);
                    MMA_BF16(acc[mt][nt * 2 + 1], ah[mt], bh[nt][2], bh[nt][3]);
                    MMA_BF16(acc[mt][nt * 2 + 0], ah[mt], bl[nt][0], bl[nt][1]);
                    MMA_BF16(acc[mt][nt * 2 + 1], ah[mt], bl[nt][2], bl[nt][3]);
                }
#pragma unroll
            for (int mt = 0; mt < 2; mt++)
                LDSM_X4(ah[mt], aL + (uint32_t)(((aRowL + mt * 16) * 40 + aColL + k16 * 16) * 2));
#pragma unroll
            for (int mt = 0; mt < 2; mt++)
#pragma unroll
                for (int nt = 0; nt < 2; nt++) {
                    MMA_BF16(acc[mt][nt * 2 + 0], ah[mt], bh[nt][0], bh[nt][1]);
                    MMA_BF16(acc[mt][nt * 2 + 1], ah[mt], bh[nt][2], bh[nt][3]);
                }
        }
    };

    issue(0, 0); CP_COMMIT();
    issue(1, 1); CP_COMMIT();
    for (int c = 0; c < nch; c++) {
        CP_WAIT1();
        __syncthreads();
        const int nc = c + 2;
        if (nc < nch) issue(nc, nc % NSTAGE);
        CP_COMMIT();
        compute(c % NSTAGE);
    }
    CP_WAIT0();

    // epilogue
    const int er = lane >> 2, ec = (lane & 3) * 2;
#pragma unroll
    for (int mt = 0; mt < 2; mt++) {
        const int row0 = m0 + m_off + mt * 16 + er;
#pragma unroll
        for (int nt = 0; nt < 4; nt++) {
            const int col = n_off + nt * 8 + ec;
            float b0 = 0.f, b1 = 0.f;
            if (bias) { b0 = __ldg(&bias[col]); b1 = __ldg(&bias[col + 1]); }
            float v0 = acc[mt][nt][0] + b0, v1 = acc[mt][nt][1] + b1;
            float v2 = acc[mt][nt][2] + b0, v3 = acc[mt][nt][3] + b1;
            if (ACT) {
                v0 = fmaxf(v0, 0.f); v1 = fmaxf(v1, 0.f);
                v2 = fmaxf(v2, 0.f); v3 = fmaxf(v3, 0.f);
            }
            if (OUTF == 0) {
                if (row0 < M) *(float2*)(Cf + (size_t)row0 * ldc + col) = make_float2(v0, v1);
                if (row0 + 8 < M) *(float2*)(Cf + (size_t)(row0 + 8) * ldc + col) = make_float2(v2, v3);
            } else {
                bf16 h0 = __float2bfloat16(v0), h1 = __float2bfloat16(v1);
                bf16 h2 = __float2bfloat16(v2), h3 = __float2bfloat16(v3);
                bf162 hA; hA.x = h0; hA.y = h1;
                bf162 hB; hB.x = h2; hB.y = h3;
                bf162 lA; lA.x = __float2bfloat16(v0 - __bfloat162float(h0));
                lA.y = __float2bfloat16(v1 - __bfloat162float(h1));
                bf162 lB; lB.x = __float2bfloat16(v2 - __bfloat162float(h2));
                lB.y = __float2bfloat16(v3 - __bfloat162float(h3));
                if (row0 < M) {
                    *(bf162*)(Chi + (size_t)row0 * ldc + col) = hA;
                    *(bf162*)(Clo + (size_t)row0 * ldc + col) = lA;
                }
                if (row0 + 8 < M) {
                    *(bf162*)(Chi + (size_t)(row0 + 8) * ldc + col) = hB;
                    *(bf162*)(Clo + (size_t)(row0 + 8) * ldc + col) = lB;
                }
            }
        }
    }
}

// ---------------- f32 -> hi/lo bf16 plane conversion ----------------
__global__ void conv_planes(const float* __restrict__ src, bf16* __restrict__ hi,
                            bf16* __restrict__ lo, int n4)
{
    const int i = blockIdx.x * blockDim.x + threadIdx.x;
    if (i >= n4) return;
    const float4 v = ((const float4*)src)[i];
    bf16 h0 = __float2bfloat16(v.x), h1 = __float2bfloat16(v.y);
    bf16 h2 = __float2bfloat16(v.z), h3 = __float2bfloat16(v.w);
    bf162 ha; ha.x = h0; ha.y = h1;
    bf162 hb; hb.x = h2; hb.y = h3;
    bf162 la; la.x = __float2bfloat16(v.x - __bfloat162float(h0));
    la.y = __float2bfloat16(v.y - __bfloat162float(h1));
    bf162 lb; lb.x = __float2bfloat16(v.z - __bfloat162float(h2));
    lb.y = __float2bfloat16(v.w - __bfloat162float(h3));
    ((bf162*)hi)[i * 2] = ha; ((bf162*)hi)[i * 2 + 1] = hb;
    ((bf162*)lo)[i * 2] = la; ((bf162*)lo)[i * 2 + 1] = lb;
}

// ---------------- edge-index dtype detection ----------------
__global__ void detect_kernel(const unsigned int* __restrict__ w) {
    if (threadIdx.x == 0 && blockIdx.x == 0) {
        int zeros = 0;
        for (int i = 1; i < 512; i += 2) zeros += (w[i] == 0u) ? 1 : 0;
        g_is64 = (zeros >= 200) ? 1 : 0;
    }
}
__device__ __forceinline__ int load_idx(const void* ei, long long pos, int is64) {
    if (is64) return (int)((const long long*)ei)[pos];
    return ((const int*)ei)[pos];
}

// ---------------- CSR build kernels ----------------
__global__ void zero_cnt_kernel() {
    const int i = blockIdx.x * blockDim.x + threadIdx.x;
    if (i < NN) g_cnt[i] = 0;
}
__global__ void degree_kernel(const void* __restrict__ ei) {
    const int i = blockIdx.x * blockDim.x + threadIdx.x;
    if (i < EE) {
        const int dst = load_idx(ei, (long long)EE + i, g_is64);
        if ((unsigned)dst < NN) atomicAdd(&g_cnt[dst], 1);
    }
}
__global__ void scan_kernel() {
    __shared__ int wsum[32];
    const int t = threadIdx.x, lane = t & 31, wid = t >> 5;
    int carry = 0;
    for (int base = 0; base < NN; base += 1024) {
        const int i = base + t;
        const int v = (i < NN) ? g_cnt[i] : 0;
        int x = v;
#pragma unroll
        for (int off = 1; off < 32; off <<= 1) {
            const int y = __shfl_up_sync(0xffffffffu, x, off);
            if (lane >= off) x += y;
        }
        if (lane == 31) wsum[wid] = x;
        __syncthreads();
        if (wid == 0) {
            int s = wsum[lane];
#pragma unroll
            for (int off = 1; off < 32; off <<= 1) {
                const int y = __shfl_up_sync(0xffffffffu, s, off);
                if (lane >= off) s += y;
            }
            wsum[lane] = s;
        }
        __syncthreads();
        const int woff = wid ? wsum[wid - 1] : 0;
        const int excl = carry + woff + x - v;
        if (i < NN) {
            g_rowptr[i] = excl;
            g_cur[i] = excl;
            g_dinv[i] = rsqrtf((float)v + 1.0f);
        }
        const int total = wsum[31];
        __syncthreads();
        carry += total;
    }
    if (t == 0) g_rowptr[NN] = carry;
}
__global__ void scatter_kernel(const void* __restrict__ ei) {
    const int i = blockIdx.x * blockDim.x + threadIdx.x;
    if (i < EE) {
        const int is64 = g_is64;
        const int dst = load_idx(ei, (long long)EE + i, is64);
        const int src = load_idx(ei, (long long)i, is64);
        if ((unsigned)dst < NN && (unsigned)src < NN) {
            const int pos = atomicAdd(&g_cur[dst], 1);
            if ((unsigned)pos < EE) g_srcidx[pos] = src;
        }
    }
}

// ---------------- GCN aggregation on planes: out = relu(segsum + self + bias) ----------------
__device__ __forceinline__ void unpack8(uint4 v, float* f) {
    float2 a = __bfloat1622float2(*(bf162*)&v.x);
    float2 b = __bfloat1622float2(*(bf162*)&v.y);
    float2 c = __bfloat1622float2(*(bf162*)&v.z);
    float2 d = __bfloat1622float2(*(bf162*)&v.w);
    f[0] = a.x; f[1] = a.y; f[2] = b.x; f[3] = b.y;
    f[4] = c.x; f[5] = c.y; f[6] = d.x; f[7] = d.y;
}

__global__ __launch_bounds__(256) void aggregate_kernel(
    const bf16* __restrict__ Hhi, const bf16* __restrict__ Hlo,
    const float* __restrict__ bias,
    bf16* __restrict__ Ohi, bf16* __restrict__ Olo, int ldo)
{
    const int gt = blockIdx.x * blockDim.x + threadIdx.x;
    const int node = gt >> 5, lane = gt & 31;
    if (node >= NN) return;
    const int q = lane & 15;
    const bf16* __restrict__ plane = (lane & 16) ? Hlo : Hhi;
    const float di = g_dinv[node];
    float acc[8];
    {
        const float w = di * di;
        uint4 v = *(const uint4*)(plane + (size_t)node * 128 + q * 8);
        float f[8]; unpack8(v, f);
#pragma unroll
        for (int j = 0; j < 8; j++) acc[j] = f[j] * w;
    }
    const int beg = g_rowptr[node], end = g_rowptr[node + 1];
    for (int e = beg; e < end; e++) {
        const int s = __ldg(&g_srcidx[e]);
        const float w = di * __ldg(&g_dinv[s]);
        uint4 v = *(const uint4*)(plane + (size_t)s * 128 + q * 8);
        float f[8]; unpack8(v, f);
#pragma unroll
        for (int j = 0; j < 8; j++) acc[j] = fmaf(f[j], w, acc[j]);
    }
#pragma unroll
    for (int j = 0; j < 8; j++) acc[j] += __shfl_xor_sync(0xffffffffu, acc[j], 16);
    if (lane < 16) {
        bf162 ho[4], lo[4];
#pragma unroll
        for (int j = 0; j < 4; j++) {
            const float v0 = fmaxf(acc[2 * j] + __ldg(&bias[q * 8 + 2 * j]), 0.f);
            const float v1 = fmaxf(acc[2 * j + 1] + __ldg(&bias[q * 8 + 2 * j + 1]), 0.f);
            bf16 h0 = __float2bfloat16(v0), h1 = __float2bfloat16(v1);
            ho[j].x = h0; ho[j].y = h1;
            lo[j].x = __float2bfloat16(v0 - __bfloat162float(h0));
            lo[j].y = __float2bfloat16(v1 - __bfloat162float(h1));
        }
        *(uint4*)(Ohi + (size_t)node * ldo + q * 8) = *(uint4*)ho;
        *(uint4*)(Olo + (size_t)node * ldo + q * 8) = *(uint4*)lo;
    }
}

// ---------------- final: sigmoid(comb @ out_W + out_b) ----------------
__global__ void final_kernel(const float* __restrict__ outW, const float* __restrict__ outb,
                             float* __restrict__ out)
{
    const int gt = blockIdx.x * blockDim.x + threadIdx.x;
    const int row = gt >> 5, lane = gt & 31;
    if (row >= NN) return;
    const float4 c = ((const float4*)g_comb)[(size_t)row * 32 + lane];
    const float4 w = ((const float4*)outW)[lane];
    float s = c.x * w.x + c.y * w.y + c.z * w.z + c.w * w.w;
#pragma unroll
    for (int off = 16; off; off >>= 1) s += __shfl_xor_sync(0xffffffffu, s, off);
    if (lane == 0) out[row] = 1.0f / (1.0f + expf(-(s + outb[0])));
}

// ---------------- orchestration ----------------
extern "C" void kernel_launch(void* const* d_in, const int* in_sizes, int n_in,
                              void* d_out, int out_size)
{
    const float* metadata_a = (const float*)d_in[0];
    const float* metadata_b = (const float*)d_in[1];
    const float* x_a        = (const float*)d_in[2];
    const float* x_b        = (const float*)d_in[3];
    const void*  ei_a       = d_in[4];
    const void*  ei_b       = d_in[5];
    const float* fc1_W  = (const float*)d_in[6];
    const float* fc1_b  = (const float*)d_in[7];
    const float* fc2_W  = (const float*)d_in[8];
    const float* fc2_b  = (const float*)d_in[9];
    const float* gcn1_W = (const float*)d_in[10];
    const float* gcn1_b = (const float*)d_in[11];
    const float* gcn2_W = (const float*)d_in[12];
    const float* gcn2_b = (const float*)d_in[13];
    const float* fcc_W  = (const float*)d_in[14];
    const float* fcc_b  = (const float*)d_in[15];
    const float* out_W  = (const float*)d_in[16];
    const float* out_b  = (const float*)d_in[17];
    float* out = (float*)d_out;

    bf16 *ain_hi, *ain_lo, *t_hi, *t_lo, *h_hi, *h_lo, *cat_hi, *cat_lo, *w_hi, *w_lo;
    float* p_comb;
    cudaGetSymbolAddress((void**)&ain_hi, g_ain_hi);
    cudaGetSymbolAddress((void**)&ain_lo, g_ain_lo);
    cudaGetSymbolAddress((void**)&t_hi, g_t_hi);
    cudaGetSymbolAddress((void**)&t_lo, g_t_lo);
    cudaGetSymbolAddress((void**)&h_hi, g_h_hi);
    cudaGetSymbolAddress((void**)&h_lo, g_h_lo);
    cudaGetSymbolAddress((void**)&cat_hi, g_cat_hi);
    cudaGetSymbolAddress((void**)&cat_lo, g_cat_lo);
    cudaGetSymbolAddress((void**)&w_hi, g_w_hi);
    cudaGetSymbolAddress((void**)&w_lo, g_w_lo);
    cudaGetSymbolAddress((void**)&p_comb, g_comb);

    cudaFuncSetAttribute(pgemm<1, 1>, cudaFuncAttributeMaxDynamicSharedMemorySize, SMEM_DYN);
    cudaFuncSetAttribute(pgemm<0, 1>, cudaFuncAttributeMaxDynamicSharedMemorySize, SMEM_DYN);
    cudaFuncSetAttribute(pgemm<1, 0>, cudaFuncAttributeMaxDynamicSharedMemorySize, SMEM_DYN);

    const int GG = (NN + 127) / 128;
    const int EB = (EE + 255) / 256;
    const int NB = (NN + 255) / 256;
    const int WB = (NN * 32 + 255) / 256;

    // weight plane offsets (rows): fc1 0, fc2 512, gcn1 640, gcn2 896, fcc 1024
    bf16* wfc1_hi = w_hi;              bf16* wfc1_lo = w_lo;
    bf16* wfc2_hi = w_hi + 512 * 128;  bf16* wfc2_lo = w_lo + 512 * 128;
    bf16* wg1_hi  = w_hi + 640 * 128;  bf16* wg1_lo  = w_lo + 640 * 128;
    bf16* wg2_hi  = w_hi + 896 * 128;  bf16* wg2_lo  = w_lo + 896 * 128;
    bf16* wfcc_hi = w_hi + 1024 * 128; bf16* wfcc_lo = w_lo + 1024 * 128;

    detect_kernel<<<1, 32>>>((const unsigned int*)ei_a);
    conv_planes<<<(512 * 128 / 4 + 255) / 256, 256>>>(fc1_W, wfc1_hi, wfc1_lo, 512 * 128 / 4);
    conv_planes<<<(128 * 128 / 4 + 255) / 256, 256>>>(fc2_W, wfc2_hi, wfc2_lo, 128 * 128 / 4);
    conv_planes<<<(256 * 128 / 4 + 255) / 256, 256>>>(gcn1_W, wg1_hi, wg1_lo, 256 * 128 / 4);
    conv_planes<<<(128 * 128 / 4 + 255) / 256, 256>>>(gcn2_W, wg2_hi, wg2_lo, 128 * 128 / 4);
    conv_planes<<<(512 * 128 / 4 + 255) / 256, 256>>>(fcc_W, wfcc_hi, wfcc_lo, 512 * 128 / 4);

    const int N512_4 = NN * 512 / 4, N256_4 = NN * 256 / 4;

    // MLP branch A -> cat[:, 0:128]
    conv_planes<<<(N512_4 + 255) / 256, 256>>>(metadata_a, ain_hi, ain_lo, N512_4);
    pgemm<1, 1><<<GG, 512, SMEM_DYN>>>(ain_hi, ain_lo, 512, wfc1_hi, wfc1_lo, fc1_b,
                                       nullptr, t_hi, t_lo, 128, NN, 512);
    pgemm<1, 1><<<GG, 512, SMEM_DYN>>>(t_hi, t_lo, 128, wfc2_hi, wfc2_lo, fc2_b,
                                       nullptr, cat_hi + 0, cat_lo + 0, 512, NN, 128);
    // MLP branch B -> cat[:, 128:256]
    conv_planes<<<(N512_4 + 255) / 256, 256>>>(metadata_b, ain_hi, ain_lo, N512_4);
    pgemm<1, 1><<<GG, 512, SMEM_DYN>>>(ain_hi, ain_lo, 512, wfc1_hi, wfc1_lo, fc1_b,
                                       nullptr, t_hi, t_lo, 128, NN, 512);
    pgemm<1, 1><<<GG, 512, SMEM_DYN>>>(t_hi, t_lo, 128, wfc2_hi, wfc2_lo, fc2_b,
                                       nullptr, cat_hi + 128, cat_lo + 128, 512, NN, 128);

    // GCN branch, graph A -> cat[:, 256:384]
    zero_cnt_kernel<<<NB, 256>>>();
    degree_kernel<<<EB, 256>>>(ei_a);
    scan_kernel<<<1, 1024>>>();
    scatter_kernel<<<EB, 256>>>(ei_a);
    conv_planes<<<(N256_4 + 255) / 256, 256>>>(x_a, ain_hi, ain_lo, N256_4);
    pgemm<0, 1><<<GG, 512, SMEM_DYN>>>(ain_hi, ain_lo, 256, wg1_hi, wg1_lo, nullptr,
                                       nullptr, h_hi, h_lo, 128, NN, 256);
    aggregate_kernel<<<WB, 256>>>(h_hi, h_lo, gcn1_b, t_hi, t_lo, 128);
    pgemm<0, 1><<<GG, 512, SMEM_DYN>>>(t_hi, t_lo, 128, wg2_hi, wg2_lo, nullptr,
                                       nullptr, h_hi, h_lo, 128, NN, 128);
    aggregate_kernel<<<WB, 256>>>(h_hi, h_lo, gcn2_b, cat_hi + 256, cat_lo + 256, 512);

    // GCN branch, graph B -> cat[:, 384:512]
    zero_cnt_kernel<<<NB, 256>>>();
    degree_kernel<<<EB, 256>>>(ei_b);
    scan_kernel<<<1, 1024>>>();
    scatter_kernel<<<EB, 256>>>(ei_b);
    conv_planes<<<(N256_4 + 255) / 256, 256>>>(x_b, ain_hi, ain_lo, N256_4);
    pgemm<0, 1><<<GG, 512, SMEM_DYN>>>(ain_hi, ain_lo, 256, wg1_hi, wg1_lo, nullptr,
                                       nullptr, h_hi, h_lo, 128, NN, 256);
    aggregate_kernel<<<WB, 256>>>(h_hi, h_lo, gcn1_b, t_hi, t_lo, 128);
    pgemm<0, 1><<<GG, 512, SMEM_DYN>>>(t_hi, t_lo, 128, wg2_hi, wg2_lo, nullptr,
                                       nullptr, h_hi, h_lo, 128, NN, 128);
    aggregate_kernel<<<WB, 256>>>(h_hi, h_lo, gcn2_b, cat_hi + 384, cat_lo + 384, 512);

    // combined = relu(cat @ fcc_W + b), single K=512 GEMM -> f32 comb
    pgemm<1, 0><<<GG, 512, SMEM_DYN>>>(cat_hi, cat_lo, 512, wfcc_hi, wfcc_lo, fcc_b,
                                       p_comb, nullptr, nullptr, 128, NN, 512);

    final_kernel<<<WB, 256>>>(out_W, out_b, out);
}

// round 6
// speedup vs baseline: 1.2535x; 1.2535x over previous
#include <cuda_runtime.h>
#include <cuda_bf16.h>
#include <cuda_fp16.h>
#include <cstdint>

#define NN 50000
#define EE 1600000

// ---------------- device scratch (no allocs allowed) ----------------
__device__ __align__(256) float  g_cat[NN * 512];   // [ma | mb | ga | gb] concat, ld=512
__device__ __align__(256) __half g_h16[NN * 128];   // GCN pre-aggregation features (fp16)
__device__ __align__(256) float  g_t[NN * 128];
__device__ __align__(256) float  g_comb[NN * 128];
__device__ int   g_cnt[NN];
__device__ float g_dinv[NN];
__device__ int   g_rowptr[NN + 1];
__device__ int   g_cur[NN];
__device__ int   g_srcidx[EE];
__device__ int   g_is64;

// ---------------- helpers ----------------
__device__ __forceinline__ uint32_t smem_to_u32(const void* p) {
    uint32_t a;
    asm("{ .reg .u64 t; cvta.to.shared.u64 t, %1; cvt.u32.u64 %0, t; }" : "=r"(a) : "l"(p));
    return a;
}
__device__ __forceinline__ unsigned long long pack4bf(float a, float b, float c, float d) {
    unsigned short u0 = __bfloat16_as_ushort(__float2bfloat16(a));
    unsigned short u1 = __bfloat16_as_ushort(__float2bfloat16(b));
    unsigned short u2 = __bfloat16_as_ushort(__float2bfloat16(c));
    unsigned short u3 = __bfloat16_as_ushort(__float2bfloat16(d));
    return (unsigned long long)u0 | ((unsigned long long)u1 << 16) |
           ((unsigned long long)u2 << 32) | ((unsigned long long)u3 << 48);
}
__device__ __forceinline__ float bf_res(float a) {
    return a - __bfloat162float(__float2bfloat16(a));
}

#define LDSM_X4(d, a) \
    asm volatile("ldmatrix.sync.aligned.m8n8.x4.shared.b16 {%0,%1,%2,%3}, [%4];" \
        : "=r"((d)[0]), "=r"((d)[1]), "=r"((d)[2]), "=r"((d)[3]) : "r"(a))
#define LDSM_X4_T(d, a) \
    asm volatile("ldmatrix.sync.aligned.m8n8.x4.trans.shared.b16 {%0,%1,%2,%3}, [%4];" \
        : "=r"((d)[0]), "=r"((d)[1]), "=r"((d)[2]), "=r"((d)[3]) : "r"(a))
#define MMA_BF16(c, a, b0, b1) \
    asm volatile("mma.sync.aligned.m16n8k16.row.col.f32.bf16.bf16.f32 " \
        "{%0,%1,%2,%3}, {%4,%5,%6,%7}, {%8,%9}, {%0,%1,%2,%3};" \
        : "+f"((c)[0]), "+f"((c)[1]), "+f"((c)[2]), "+f"((c)[3]) \
        : "r"((a)[0]), "r"((a)[1]), "r"((a)[2]), "r"((a)[3]), "r"(b0), "r"(b1))

// per buffer: A_hi 64x40bf16(5120B) | A_lo(5120) | B_hi 32x136bf16(8704) | B_lo(8704)
#define BUFS    27648
#define OFF_ALO 5120
#define OFF_BHI 10240
#define OFF_BLO 18944
#define SMEM_DYN (2 * BUFS)

// ---------------- HMMA split-bf16 GEMM: C[M,128] = A[M,K] @ W[K,128] ----------------
// OUTF: 0 = f32 Cf (ldc), 1 = fp16-only Ch (ld=128)
template <int ACT, int OUTF>
__global__ __launch_bounds__(256, 2) void mma_gemm(
    const float* __restrict__ A, int lda, const float* __restrict__ W,
    const float* __restrict__ bias, float* __restrict__ Cf, int ldc,
    __half* __restrict__ Ch, int M, int K)
{
    extern __shared__ char smem[];
    const uint32_t sb = smem_to_u32(smem);
    const int tid = threadIdx.x, wid = tid >> 5, lane = tid & 31;
    const int m0 = blockIdx.x * 64;
    const int m_off = (wid & 1) * 32, n_off = (wid >> 1) * 32;

    // ldmatrix lane address components
    const int mi = lane >> 3, r8 = lane & 7;
    const int aRowL = m_off + (mi & 1) * 8 + r8;
    const int aColL = (mi >> 1) * 8;
    const int bRowL = (mi & 1) * 8 + r8;
    const int bColL = n_off + (mi >> 1) * 8;

    // global load mapping: A 64x32 f32 = 512 float4 (2/thr); B 32x128 = 1024 float4 (4/thr)
    int aRow[2], aK[2], bRow[4], bN[4];
#pragma unroll
    for (int i = 0; i < 2; i++) {
        const int f = tid * 2 + i;
        aRow[i] = f >> 3; aK[i] = (f & 7) * 4;
    }
#pragma unroll
    for (int i = 0; i < 4; i++) {
        const int f = tid + i * 256;
        bRow[i] = f >> 5; bN[i] = (f & 31) * 4;
    }

    float acc[2][4][4];
#pragma unroll
    for (int mt = 0; mt < 2; mt++)
#pragma unroll
        for (int nt = 0; nt < 4; nt++)
#pragma unroll
            for (int j = 0; j < 4; j++) acc[mt][nt][j] = 0.f;

    float4 ra[2], rb[4];
    const int nch = K >> 5;

    auto gload = [&](int c) {
#pragma unroll
        for (int i = 0; i < 2; i++) {
            ra[i] = make_float4(0.f, 0.f, 0.f, 0.f);
            if (m0 + aRow[i] < M)
                ra[i] = *(const float4*)(A + (size_t)(m0 + aRow[i]) * lda + c * 32 + aK[i]);
        }
#pragma unroll
        for (int i = 0; i < 4; i++)
            rb[i] = *(const float4*)(W + (size_t)(c * 32 + bRow[i]) * 128 + bN[i]);
    };
    auto sstore = [&](int b) {
        char* base = smem + b * BUFS;
#pragma unroll
        for (int i = 0; i < 2; i++) {
            const uint32_t off = (uint32_t)(aRow[i] * 80 + aK[i] * 2);
            *(unsigned long long*)(base + off) = pack4bf(ra[i].x, ra[i].y, ra[i].z, ra[i].w);
            *(unsigned long long*)(base + OFF_ALO + off) =
                pack4bf(bf_res(ra[i].x), bf_res(ra[i].y), bf_res(ra[i].z), bf_res(ra[i].w));
        }
#pragma unroll
        for (int i = 0; i < 4; i++) {
            const uint32_t boff = (uint32_t)(bRow[i] * 272 + bN[i] * 2);
            *(unsigned long long*)(base + OFF_BHI + boff) = pack4bf(rb[i].x, rb[i].y, rb[i].z, rb[i].w);
            *(unsigned long long*)(base + OFF_BLO + boff) =
                pack4bf(bf_res(rb[i].x), bf_res(rb[i].y), bf_res(rb[i].z), bf_res(rb[i].w));
        }
    };
    auto compute = [&](int b) {
        const uint32_t aH = sb + b * BUFS;
        const uint32_t aL = aH + OFF_ALO;
        const uint32_t bH = aH + OFF_BHI;
#pragma unroll
        for (int k16 = 0; k16 < 2; k16++) {
            uint32_t ah[2][4], bh[2][4], bl[2][4];
#pragma unroll
            for (int mt = 0; mt < 2; mt++)
                LDSM_X4(ah[mt], aH + (uint32_t)(((aRowL + mt * 16) * 40 + aColL + k16 * 16) * 2));
#pragma unroll
            for (int nt = 0; nt < 2; nt++) {
                const uint32_t ba = bH +
                    (uint32_t)(((bRowL + k16 * 16) * 136 + bColL + nt * 16) * 2);
                LDSM_X4_T(bh[nt], ba);
                LDSM_X4_T(bl[nt], ba + (OFF_BLO - OFF_BHI));
            }
#pragma unroll
            for (int mt = 0; mt < 2; mt++)
#pragma unroll
                for (int nt = 0; nt < 2; nt++) {
                    MMA_BF16(acc[mt][nt * 2 + 0], ah[mt], bh[nt][0], bh[nt][1]);
                    MMA_BF16(acc[mt][nt * 2 + 1], ah[mt], bh[nt][2], bh[nt][3]);
                    MMA_BF16(acc[mt][nt * 2 + 0], ah[mt], bl[nt][0], bl[nt][1]);
                    MMA_BF16(acc[mt][nt * 2 + 1], ah[mt], bl[nt][2], bl[nt][3]);
                }
#pragma unroll
            for (int mt = 0; mt < 2; mt++)
                LDSM_X4(ah[mt], aL + (uint32_t)(((aRowL + mt * 16) * 40 + aColL + k16 * 16) * 2));
#pragma unroll
            for (int mt = 0; mt < 2; mt++)
#pragma unroll
                for (int nt = 0; nt < 2; nt++) {
                    MMA_BF16(acc[mt][nt * 2 + 0], ah[mt], bh[nt][0], bh[nt][1]);
                    MMA_BF16(acc[mt][nt * 2 + 1], ah[mt], bh[nt][2], bh[nt][3]);
                }
        }
    };

    gload(0);
    sstore(0);
    __syncthreads();
    for (int c = 0; c < nch; c++) {
        if (c + 1 < nch) gload(c + 1);
        compute(c & 1);
        if (c + 1 < nch) {
            __syncthreads();
            sstore((c + 1) & 1);
            __syncthreads();
        }
    }

    // epilogue
    const int er = lane >> 2, ec = (lane & 3) * 2;
#pragma unroll
    for (int mt = 0; mt < 2; mt++) {
        const int row0 = m0 + m_off + mt * 16 + er;
#pragma unroll
        for (int nt = 0; nt < 4; nt++) {
            const int col = n_off + nt * 8 + ec;
            float b0 = 0.f, b1 = 0.f;
            if (bias) { b0 = __ldg(&bias[col]); b1 = __ldg(&bias[col + 1]); }
            float v0 = acc[mt][nt][0] + b0, v1 = acc[mt][nt][1] + b1;
            float v2 = acc[mt][nt][2] + b0, v3 = acc[mt][nt][3] + b1;
            if (ACT) {
                v0 = fmaxf(v0, 0.f); v1 = fmaxf(v1, 0.f);
                v2 = fmaxf(v2, 0.f); v3 = fmaxf(v3, 0.f);
            }
            if (OUTF == 0) {
                if (row0 < M) *(float2*)(Cf + (size_t)row0 * ldc + col) = make_float2(v0, v1);
                if (row0 + 8 < M) *(float2*)(Cf + (size_t)(row0 + 8) * ldc + col) = make_float2(v2, v3);
            } else {
                if (row0 < M)
                    *(__half2*)(Ch + (size_t)row0 * 128 + col) = __floats2half2_rn(v0, v1);
                if (row0 + 8 < M)
                    *(__half2*)(Ch + (size_t)(row0 + 8) * 128 + col) = __floats2half2_rn(v2, v3);
            }
        }
    }
}

// ---------------- edge-index dtype detection ----------------
__global__ void detect_kernel(const unsigned int* __restrict__ w) {
    if (threadIdx.x == 0 && blockIdx.x == 0) {
        int zeros = 0;
        for (int i = 1; i < 512; i += 2) zeros += (w[i] == 0u) ? 1 : 0;
        g_is64 = (zeros >= 200) ? 1 : 0;
    }
}
__device__ __forceinline__ int load_idx(const void* ei, long long pos, int is64) {
    if (is64) return (int)((const long long*)ei)[pos];
    return ((const int*)ei)[pos];
}

// ---------------- CSR build kernels ----------------
__global__ void zero_cnt_kernel() {
    const int i = blockIdx.x * blockDim.x + threadIdx.x;
    if (i < NN) g_cnt[i] = 0;
}
__global__ void degree_kernel(const void* __restrict__ ei) {
    const int i = blockIdx.x * blockDim.x + threadIdx.x;
    if (i < EE) {
        const int dst = load_idx(ei, (long long)EE + i, g_is64);
        if ((unsigned)dst < NN) atomicAdd(&g_cnt[dst], 1);
    }
}
__global__ void scan_kernel() {
    __shared__ int wsum[32];
    const int t = threadIdx.x, lane = t & 31, wid = t >> 5;
    int carry = 0;
    for (int base = 0; base < NN; base += 1024) {
        const int i = base + t;
        const int v = (i < NN) ? g_cnt[i] : 0;
        int x = v;
#pragma unroll
        for (int off = 1; off < 32; off <<= 1) {
            const int y = __shfl_up_sync(0xffffffffu, x, off);
            if (lane >= off) x += y;
        }
        if (lane == 31) wsum[wid] = x;
        __syncthreads();
        if (wid == 0) {
            int s = wsum[lane];
#pragma unroll
            for (int off = 1; off < 32; off <<= 1) {
                const int y = __shfl_up_sync(0xffffffffu, s, off);
                if (lane >= off) s += y;
            }
            wsum[lane] = s;
        }
        __syncthreads();
        const int woff = wid ? wsum[wid - 1] : 0;
        const int excl = carry + woff + x - v;
        if (i < NN) {
            g_rowptr[i] = excl;
            g_cur[i] = excl;
            g_dinv[i] = rsqrtf((float)v + 1.0f);
        }
        const int total = wsum[31];
        __syncthreads();
        carry += total;
    }
    if (t == 0) g_rowptr[NN] = carry;
}
__global__ void scatter_kernel(const void* __restrict__ ei) {
    const int i = blockIdx.x * blockDim.x + threadIdx.x;
    if (i < EE) {
        const int is64 = g_is64;
        const int dst = load_idx(ei, (long long)EE + i, is64);
        const int src = load_idx(ei, (long long)i, is64);
        if ((unsigned)dst < NN && (unsigned)src < NN) {
            const int pos = atomicAdd(&g_cur[dst], 1);
            if ((unsigned)pos < EE) g_srcidx[pos] = src;
        }
    }
}

// ---------------- GCN aggregation: fp16 gather, f32 out ----------------
__global__ __launch_bounds__(256) void aggregate_kernel(
    const __half* __restrict__ H, const float* __restrict__ bias,
    float* __restrict__ out, int ldo)
{
    const int gt = blockIdx.x * blockDim.x + threadIdx.x;
    const int node = gt >> 5, lane = gt & 31;
    if (node >= NN) return;
    const float di = g_dinv[node];
    float acc[4];
    {
        const float w = di * di;  // self-loop norm
        const uint2 v = *(const uint2*)(H + (size_t)node * 128 + lane * 4);
        const float2 f0 = __half22float2(*(const __half2*)&v.x);
        const float2 f1 = __half22float2(*(const __half2*)&v.y);
        acc[0] = f0.x * w; acc[1] = f0.y * w; acc[2] = f1.x * w; acc[3] = f1.y * w;
    }
    const int beg = g_rowptr[node], end = g_rowptr[node + 1];
    for (int e = beg; e < end; e++) {
        const int s = __ldg(&g_srcidx[e]);
        const float w = di * __ldg(&g_dinv[s]);
        const uint2 v = *(const uint2*)(H + (size_t)s * 128 + lane * 4);
        const float2 f0 = __half22float2(*(const __half2*)&v.x);
        const float2 f1 = __half22float2(*(const __half2*)&v.y);
        acc[0] = fmaf(f0.x, w, acc[0]);
        acc[1] = fmaf(f0.y, w, acc[1]);
        acc[2] = fmaf(f1.x, w, acc[2]);
        acc[3] = fmaf(f1.y, w, acc[3]);
    }
    const float4 b = *(const float4*)(bias + lane * 4);
    *(float4*)(out + (size_t)node * ldo + lane * 4) =
        make_float4(fmaxf(acc[0] + b.x, 0.f), fmaxf(acc[1] + b.y, 0.f),
                    fmaxf(acc[2] + b.z, 0.f), fmaxf(acc[3] + b.w, 0.f));
}

// ---------------- final: sigmoid(comb @ out_W + out_b) ----------------
__global__ void final_kernel(const float* __restrict__ outW, const float* __restrict__ outb,
                             float* __restrict__ out)
{
    const int gt = blockIdx.x * blockDim.x + threadIdx.x;
    const int row = gt >> 5, lane = gt & 31;
    if (row >= NN) return;
    const float4 c = ((const float4*)g_comb)[(size_t)row * 32 + lane];
    const float4 w = ((const float4*)outW)[lane];
    float s = c.x * w.x + c.y * w.y + c.z * w.z + c.w * w.w;
#pragma unroll
    for (int off = 16; off; off >>= 1) s += __shfl_xor_sync(0xffffffffu, s, off);
    if (lane == 0) out[row] = 1.0f / (1.0f + expf(-(s + outb[0])));
}

// ---------------- orchestration ----------------
extern "C" void kernel_launch(void* const* d_in, const int* in_sizes, int n_in,
                              void* d_out, int out_size)
{
    const float* metadata_a = (const float*)d_in[0];
    const float* metadata_b = (const float*)d_in[1];
    const float* x_a        = (const float*)d_in[2];
    const float* x_b        = (const float*)d_in[3];
    const void*  ei_a       = d_in[4];
    const void*  ei_b       = d_in[5];
    const float* fc1_W  = (const float*)d_in[6];
    const float* fc1_b  = (const float*)d_in[7];
    const float* fc2_W  = (const float*)d_in[8];
    const float* fc2_b  = (const float*)d_in[9];
    const float* gcn1_W = (const float*)d_in[10];
    const float* gcn1_b = (const float*)d_in[11];
    const float* gcn2_W = (const float*)d_in[12];
    const float* gcn2_b = (const float*)d_in[13];
    const float* fcc_W  = (const float*)d_in[14];
    const float* fcc_b  = (const float*)d_in[15];
    const float* out_W  = (const float*)d_in[16];
    const float* out_b  = (const float*)d_in[17];
    float* out = (float*)d_out;

    float *p_cat, *p_t, *p_comb;
    __half* p_h16;
    cudaGetSymbolAddress((void**)&p_cat, g_cat);
    cudaGetSymbolAddress((void**)&p_t, g_t);
    cudaGetSymbolAddress((void**)&p_comb, g_comb);
    cudaGetSymbolAddress((void**)&p_h16, g_h16);

    cudaFuncSetAttribute(mma_gemm<1, 0>, cudaFuncAttributeMaxDynamicSharedMemorySize, SMEM_DYN);
    cudaFuncSetAttribute(mma_gemm<0, 1>, cudaFuncAttributeMaxDynamicSharedMemorySize, SMEM_DYN);

    const int GG = (NN + 63) / 64;            // 782
    const int EB = (EE + 255) / 256;
    const int NB = (NN + 255) / 256;
    const int WB = (NN * 32 + 255) / 256;

    detect_kernel<<<1, 32>>>((const unsigned int*)ei_a);

    // MLP branches -> g_cat[:, 0:128] and [:, 128:256]
    mma_gemm<1, 0><<<GG, 256, SMEM_DYN>>>(metadata_a, 512, fc1_W, fc1_b, p_t, 128, nullptr, NN, 512);
    mma_gemm<1, 0><<<GG, 256, SMEM_DYN>>>(p_t, 128, fc2_W, fc2_b, p_cat + 0, 512, nullptr, NN, 128);
    mma_gemm<1, 0><<<GG, 256, SMEM_DYN>>>(metadata_b, 512, fc1_W, fc1_b, p_t, 128, nullptr, NN, 512);
    mma_gemm<1, 0><<<GG, 256, SMEM_DYN>>>(p_t, 128, fc2_W, fc2_b, p_cat + 128, 512, nullptr, NN, 128);

    // GCN branch, graph A -> g_cat[:, 256:384]
    zero_cnt_kernel<<<NB, 256>>>();
    degree_kernel<<<EB, 256>>>(ei_a);
    scan_kernel<<<1, 1024>>>();
    scatter_kernel<<<EB, 256>>>(ei_a);
    mma_gemm<0, 1><<<GG, 256, SMEM_DYN>>>(x_a, 256, gcn1_W, nullptr, nullptr, 128, p_h16, NN, 256);
    aggregate_kernel<<<WB, 256>>>(p_h16, gcn1_b, p_t, 128);
    mma_gemm<0, 1><<<GG, 256, SMEM_DYN>>>(p_t, 128, gcn2_W, nullptr, nullptr, 128, p_h16, NN, 128);
    aggregate_kernel<<<WB, 256>>>(p_h16, gcn2_b, p_cat + 256, 512);

    // GCN branch, graph B -> g_cat[:, 384:512]
    zero_cnt_kernel<<<NB, 256>>>();
    degree_kernel<<<EB, 256>>>(ei_b);
    scan_kernel<<<1, 1024>>>();
    scatter_kernel<<<EB, 256>>>(ei_b);
    mma_gemm<0, 1><<<GG, 256, SMEM_DYN>>>(x_b, 256, gcn1_W, nullptr, nullptr, 128, p_h16, NN, 256);
    aggregate_kernel<<<WB, 256>>>(p_h16, gcn1_b, p_t, 128);
    mma_gemm<0, 1><<<GG, 256, SMEM_DYN>>>(p_t, 128, gcn2_W, nullptr, nullptr, 128, p_h16, NN, 128);
    aggregate_kernel<<<WB, 256>>>(p_h16, gcn2_b, p_cat + 384, 512);

    // combined = relu(cat @ fcc_W + b), single K=512 GEMM
    mma_gemm<1, 0><<<GG, 256, SMEM_DYN>>>(p_cat, 512, fcc_W, fcc_b, p_comb, 128, nullptr, NN, 512);

    final_kernel<<<WB, 256>>>(out_W, out_b, out);
}

// round 7
// speedup vs baseline: 1.3227x; 1.0552x over previous
#include <cuda_runtime.h>
#include <cuda_bf16.h>
#include <cuda_fp16.h>
#include <cstdint>

#define NN 50000
#define EE 1600000

typedef __nv_bfloat16 bf16;
typedef __nv_bfloat162 bf162;

// ---------------- device scratch (no allocs allowed) ----------------
__device__ __align__(256) float  g_cat[NN * 512];   // [ma | mb | ga | gb] concat, ld=512
__device__ __align__(256) __half g_h16[NN * 128];   // GCN pre-aggregation features (fp16)
__device__ __align__(256) float  g_t[NN * 128];
__device__ __align__(256) float  g_comb[NN * 128];
__device__ __align__(256) bf16   g_whi[1536 * 128]; // weight hi planes
__device__ __align__(256) bf16   g_wlo[1536 * 128]; // weight lo planes
__device__ int   g_cnt[NN];
__device__ float g_dinv[NN];
__device__ int   g_rowptr[NN + 1];
__device__ int   g_cur[NN];
__device__ int   g_srcidx[EE];
__device__ int   g_is64;

// ---------------- helpers ----------------
__device__ __forceinline__ uint32_t smem_to_u32(const void* p) {
    uint32_t a;
    asm("{ .reg .u64 t; cvta.to.shared.u64 t, %1; cvt.u32.u64 %0, t; }" : "=r"(a) : "l"(p));
    return a;
}
__device__ __forceinline__ void cpa16(uint32_t d, const void* s) {
    asm volatile("cp.async.cg.shared.global [%0], [%1], 16;" :: "r"(d), "l"(s) : "memory");
}
#define CP_COMMIT() asm volatile("cp.async.commit_group;" ::: "memory")
#define CP_WAIT1()  asm volatile("cp.async.wait_group 1;" ::: "memory")
#define CP_WAIT0()  asm volatile("cp.async.wait_group 0;" ::: "memory")

// f32x4 -> packed bf16 hi + lo (split precision)
__device__ __forceinline__ void cvt_hilo(float4 v, unsigned long long& hi, unsigned long long& lo) {
    union { unsigned long long u; bf162 b[2]; } H, L;
    H.b[0] = __floats2bfloat162_rn(v.x, v.y);
    H.b[1] = __floats2bfloat162_rn(v.z, v.w);
    const float2 f0 = __bfloat1622float2(H.b[0]);
    const float2 f1 = __bfloat1622float2(H.b[1]);
    L.b[0] = __floats2bfloat162_rn(v.x - f0.x, v.y - f0.y);
    L.b[1] = __floats2bfloat162_rn(v.z - f1.x, v.w - f1.y);
    hi = H.u; lo = L.u;
}

#define LDSM_X4(d, a) \
    asm volatile("ldmatrix.sync.aligned.m8n8.x4.shared.b16 {%0,%1,%2,%3}, [%4];" \
        : "=r"((d)[0]), "=r"((d)[1]), "=r"((d)[2]), "=r"((d)[3]) : "r"(a))
#define LDSM_X4_T(d, a) \
    asm volatile("ldmatrix.sync.aligned.m8n8.x4.trans.shared.b16 {%0,%1,%2,%3}, [%4];" \
        : "=r"((d)[0]), "=r"((d)[1]), "=r"((d)[2]), "=r"((d)[3]) : "r"(a))
#define MMA_BF16(c, a, b0, b1) \
    asm volatile("mma.sync.aligned.m16n8k16.row.col.f32.bf16.bf16.f32 " \
        "{%0,%1,%2,%3}, {%4,%5,%6,%7}, {%8,%9}, {%0,%1,%2,%3};" \
        : "+f"((c)[0]), "+f"((c)[1]), "+f"((c)[2]), "+f"((c)[3]) \
        : "r"((a)[0]), "r"((a)[1]), "r"((a)[2]), "r"((a)[3]), "r"(b0), "r"(b1))

// per buffer: A_hi 64x40bf16(5120B) | A_lo(5120) | B_hi 32x136bf16(8704) | B_lo(8704)
#define BUFS    27648
#define OFF_ALO 5120
#define OFF_BHI 10240
#define OFF_BLO 18944
#define SMEM_DYN (2 * BUFS)

// ---------------- HMMA split-bf16 GEMM: C[M,128] = A[M,K] @ W[K,128] ----------------
// OUTF: 0 = f32 Cf (ldc), 1 = fp16-only Ch (ld=128). Weights arrive pre-split (bf16 hi/lo).
template <int ACT, int OUTF>
__global__ __launch_bounds__(256, 2) void mma_gemm(
    const float* __restrict__ A, int lda,
    const bf16* __restrict__ Whi, const bf16* __restrict__ Wlo,
    const float* __restrict__ bias, float* __restrict__ Cf, int ldc,
    __half* __restrict__ Ch, int M, int K)
{
    extern __shared__ char smem[];
    const uint32_t sb = smem_to_u32(smem);
    const int tid = threadIdx.x, wid = tid >> 5, lane = tid & 31;
    const int m0 = blockIdx.x * 64;
    const int m_off = (wid & 1) * 32, n_off = (wid >> 1) * 32;

    // ldmatrix lane address components
    const int mi = lane >> 3, r8 = lane & 7;
    const int aRowL = m_off + (mi & 1) * 8 + r8;
    const int aColL = (mi >> 1) * 8;
    const int bRowL = (mi & 1) * 8 + r8;
    const int bColL = n_off + (mi >> 1) * 8;

    // A global load mapping: 64x32 f32 = 512 float4, 2/thread
    int aRow[2], aK[2];
#pragma unroll
    for (int i = 0; i < 2; i++) {
        const int f = tid * 2 + i;
        aRow[i] = f >> 3; aK[i] = (f & 7) * 4;
    }

    float acc[2][4][4];
#pragma unroll
    for (int mt = 0; mt < 2; mt++)
#pragma unroll
        for (int nt = 0; nt < 4; nt++)
#pragma unroll
            for (int j = 0; j < 4; j++) acc[mt][nt][j] = 0.f;

    float4 ra[2];
    const int nch = K >> 5;

    auto gloadA = [&](int c) {
#pragma unroll
        for (int i = 0; i < 2; i++) {
            ra[i] = make_float4(0.f, 0.f, 0.f, 0.f);
            if (m0 + aRow[i] < M)
                ra[i] = *(const float4*)(A + (size_t)(m0 + aRow[i]) * lda + c * 32 + aK[i]);
        }
    };
    auto issueB = [&](int c, int slot) {
        const uint32_t base = sb + slot * BUFS;
#pragma unroll
        for (int i = 0; i < 2; i++) {
            const int f = tid + i * 256;
            const int br = f >> 4, bq = f & 15;
            const size_t off = (size_t)(c * 32 + br) * 128 + bq * 8;
            cpa16(base + OFF_BHI + br * 272 + bq * 16, Whi + off);
            cpa16(base + OFF_BLO + br * 272 + bq * 16, Wlo + off);
        }
    };
    auto sstoreA = [&](int b) {
        char* base = smem + b * BUFS;
#pragma unroll
        for (int i = 0; i < 2; i++) {
            const uint32_t off = (uint32_t)(aRow[i] * 80 + aK[i] * 2);
            unsigned long long hi, lo;
            cvt_hilo(ra[i], hi, lo);
            *(unsigned long long*)(base + off) = hi;
            *(unsigned long long*)(base + OFF_ALO + off) = lo;
        }
    };
    auto compute = [&](int b) {
        const uint32_t aH = sb + b * BUFS;
        const uint32_t aL = aH + OFF_ALO;
        const uint32_t bH = aH + OFF_BHI;
#pragma unroll
        for (int k16 = 0; k16 < 2; k16++) {
            uint32_t ah[2][4], bh[2][4], bl[2][4];
#pragma unroll
            for (int mt = 0; mt < 2; mt++)
                LDSM_X4(ah[mt], aH + (uint32_t)(((aRowL + mt * 16) * 40 + aColL + k16 * 16) * 2));
#pragma unroll
            for (int nt = 0; nt < 2; nt++) {
                const uint32_t ba = bH +
                    (uint32_t)(((bRowL + k16 * 16) * 136 + bColL + nt * 16) * 2);
                LDSM_X4_T(bh[nt], ba);
                LDSM_X4_T(bl[nt], ba + (OFF_BLO - OFF_BHI));
            }
#pragma unroll
            for (int mt = 0; mt < 2; mt++)
#pragma unroll
                for (int nt = 0; nt < 2; nt++) {
                    MMA_BF16(acc[mt][nt * 2 + 0], ah[mt], bh[nt][0], bh[nt][1]);
                    MMA_BF16(acc[mt][nt * 2 + 1], ah[mt], bh[nt][2], bh[nt][3]);
                    MMA_BF16(acc[mt][nt * 2 + 0], ah[mt], bl[nt][0], bl[nt][1]);
                    MMA_BF16(acc[mt][nt * 2 + 1], ah[mt], bl[nt][2], bl[nt][3]);
                }
#pragma unroll
            for (int mt = 0; mt < 2; mt++)
                LDSM_X4(ah[mt], aL + (uint32_t)(((aRowL + mt * 16) * 40 + aColL + k16 * 16) * 2));
#pragma unroll
            for (int mt = 0; mt < 2; mt++)
#pragma unroll
                for (int nt = 0; nt < 2; nt++) {
                    MMA_BF16(acc[mt][nt * 2 + 0], ah[mt], bh[nt][0], bh[nt][1]);
                    MMA_BF16(acc[mt][nt * 2 + 1], ah[mt], bh[nt][2], bh[nt][3]);
                }
        }
    };

    gloadA(0);
    issueB(0, 0); CP_COMMIT();
    sstoreA(0);
    for (int c = 0; c < nch; c++) {
        if (c + 1 < nch) {
            gloadA(c + 1);
            issueB(c + 1, (c + 1) & 1); CP_COMMIT();
            CP_WAIT1();
        } else {
            CP_WAIT0();
        }
        __syncthreads();
        compute(c & 1);
        if (c + 1 < nch) {
            __syncthreads();
            sstoreA((c + 1) & 1);
        }
    }

    // epilogue
    const int er = lane >> 2, ec = (lane & 3) * 2;
#pragma unroll
    for (int mt = 0; mt < 2; mt++) {
        const int row0 = m0 + m_off + mt * 16 + er;
#pragma unroll
        for (int nt = 0; nt < 4; nt++) {
            const int col = n_off + nt * 8 + ec;
            float b0 = 0.f, b1 = 0.f;
            if (bias) { b0 = __ldg(&bias[col]); b1 = __ldg(&bias[col + 1]); }
            float v0 = acc[mt][nt][0] + b0, v1 = acc[mt][nt][1] + b1;
            float v2 = acc[mt][nt][2] + b0, v3 = acc[mt][nt][3] + b1;
            if (ACT) {
                v0 = fmaxf(v0, 0.f); v1 = fmaxf(v1, 0.f);
                v2 = fmaxf(v2, 0.f); v3 = fmaxf(v3, 0.f);
            }
            if (OUTF == 0) {
                if (row0 < M) *(float2*)(Cf + (size_t)row0 * ldc + col) = make_float2(v0, v1);
                if (row0 + 8 < M) *(float2*)(Cf + (size_t)(row0 + 8) * ldc + col) = make_float2(v2, v3);
            } else {
                if (row0 < M)
                    *(__half2*)(Ch + (size_t)row0 * 128 + col) = __floats2half2_rn(v0, v1);
                if (row0 + 8 < M)
                    *(__half2*)(Ch + (size_t)(row0 + 8) * 128 + col) = __floats2half2_rn(v2, v3);
            }
        }
    }
}

// ---------------- weight f32 -> bf16 hi/lo planes ----------------
__global__ void conv_w(const float* __restrict__ src, bf16* __restrict__ hi,
                       bf16* __restrict__ lo, int n4)
{
    const int i = blockIdx.x * blockDim.x + threadIdx.x;
    if (i >= n4) return;
    const float4 v = ((const float4*)src)[i];
    unsigned long long h, l;
    cvt_hilo(v, h, l);
    ((unsigned long long*)hi)[i] = h;
    ((unsigned long long*)lo)[i] = l;
}

// ---------------- edge-index dtype detection ----------------
__global__ void detect_kernel(const unsigned int* __restrict__ w) {
    if (threadIdx.x == 0 && blockIdx.x == 0) {
        int zeros = 0;
        for (int i = 1; i < 512; i += 2) zeros += (w[i] == 0u) ? 1 : 0;
        g_is64 = (zeros >= 200) ? 1 : 0;
    }
}
__device__ __forceinline__ int load_idx(const void* ei, long long pos, int is64) {
    if (is64) return (int)((const long long*)ei)[pos];
    return ((const int*)ei)[pos];
}

// ---------------- CSR build kernels ----------------
__global__ void zero_cnt_kernel() {
    const int i = blockIdx.x * blockDim.x + threadIdx.x;
    if (i < NN) g_cnt[i] = 0;
}
__global__ void degree_kernel(const void* __restrict__ ei) {
    const int i = blockIdx.x * blockDim.x + threadIdx.x;
    if (i < EE) {
        const int dst = load_idx(ei, (long long)EE + i, g_is64);
        if ((unsigned)dst < NN) atomicAdd(&g_cnt[dst], 1);
    }
}
__global__ void scan_kernel() {
    __shared__ int wsum[32];
    const int t = threadIdx.x, lane = t & 31, wid = t >> 5;
    int carry = 0;
    for (int base = 0; base < NN; base += 1024) {
        const int i = base + t;
        const int v = (i < NN) ? g_cnt[i] : 0;
        int x = v;
#pragma unroll
        for (int off = 1; off < 32; off <<= 1) {
            const int y = __shfl_up_sync(0xffffffffu, x, off);
            if (lane >= off) x += y;
        }
        if (lane == 31) wsum[wid] = x;
        __syncthreads();
        if (wid == 0) {
            int s = wsum[lane];
#pragma unroll
            for (int off = 1; off < 32; off <<= 1) {
                const int y = __shfl_up_sync(0xffffffffu, s, off);
                if (lane >= off) s += y;
            }
            wsum[lane] = s;
        }
        __syncthreads();
        const int woff = wid ? wsum[wid - 1] : 0;
        const int excl = carry + woff + x - v;
        if (i < NN) {
            g_rowptr[i] = excl;
            g_cur[i] = excl;
            g_dinv[i] = rsqrtf((float)v + 1.0f);
        }
        const int total = wsum[31];
        __syncthreads();
        carry += total;
    }
    if (t == 0) g_rowptr[NN] = carry;
}
__global__ void scatter_kernel(const void* __restrict__ ei) {
    const int i = blockIdx.x * blockDim.x + threadIdx.x;
    if (i < EE) {
        const int is64 = g_is64;
        const int dst = load_idx(ei, (long long)EE + i, is64);
        const int src = load_idx(ei, (long long)i, is64);
        if ((unsigned)dst < NN && (unsigned)src < NN) {
            const int pos = atomicAdd(&g_cur[dst], 1);
            if ((unsigned)pos < EE) g_srcidx[pos] = src;
        }
    }
}

// ---------------- GCN aggregation: fp16 gather, f32 out ----------------
__global__ __launch_bounds__(256) void aggregate_kernel(
    const __half* __restrict__ H, const float* __restrict__ bias,
    float* __restrict__ out, int ldo)
{
    const int gt = blockIdx.x * blockDim.x + threadIdx.x;
    const int node = gt >> 5, lane = gt & 31;
    if (node >= NN) return;
    const float di = g_dinv[node];
    float acc[4];
    {
        const float w = di * di;  // self-loop norm
        const uint2 v = *(const uint2*)(H + (size_t)node * 128 + lane * 4);
        const float2 f0 = __half22float2(*(const __half2*)&v.x);
        const float2 f1 = __half22float2(*(const __half2*)&v.y);
        acc[0] = f0.x * w; acc[1] = f0.y * w; acc[2] = f1.x * w; acc[3] = f1.y * w;
    }
    const int beg = g_rowptr[node], end = g_rowptr[node + 1];
    for (int e = beg; e < end; e++) {
        const int s = __ldg(&g_srcidx[e]);
        const float w = di * __ldg(&g_dinv[s]);
        const uint2 v = *(const uint2*)(H + (size_t)s * 128 + lane * 4);
        const float2 f0 = __half22float2(*(const __half2*)&v.x);
        const float2 f1 = __half22float2(*(const __half2*)&v.y);
        acc[0] = fmaf(f0.x, w, acc[0]);
        acc[1] = fmaf(f0.y, w, acc[1]);
        acc[2] = fmaf(f1.x, w, acc[2]);
        acc[3] = fmaf(f1.y, w, acc[3]);
    }
    const float4 b = *(const float4*)(bias + lane * 4);
    *(float4*)(out + (size_t)node * ldo + lane * 4) =
        make_float4(fmaxf(acc[0] + b.x, 0.f), fmaxf(acc[1] + b.y, 0.f),
                    fmaxf(acc[2] + b.z, 0.f), fmaxf(acc[3] + b.w, 0.f));
}

// ---------------- final: sigmoid(comb @ out_W + out_b) ----------------
__global__ void final_kernel(const float* __restrict__ outW, const float* __restrict__ outb,
                             float* __restrict__ out)
{
    const int gt = blockIdx.x * blockDim.x + threadIdx.x;
    const int row = gt >> 5, lane = gt & 31;
    if (row >= NN) return;
    const float4 c = ((const float4*)g_comb)[(size_t)row * 32 + lane];
    const float4 w = ((const float4*)outW)[lane];
    float s = c.x * w.x + c.y * w.y + c.z * w.z + c.w * w.w;
#pragma unroll
    for (int off = 16; off; off >>= 1) s += __shfl_xor_sync(0xffffffffu, s, off);
    if (lane == 0) out[row] = 1.0f / (1.0f + expf(-(s + outb[0])));
}

// ---------------- orchestration ----------------
extern "C" void kernel_launch(void* const* d_in, const int* in_sizes, int n_in,
                              void* d_out, int out_size)
{
    const float* metadata_a = (const float*)d_in[0];
    const float* metadata_b = (const float*)d_in[1];
    const float* x_a        = (const float*)d_in[2];
    const float* x_b        = (const float*)d_in[3];
    const void*  ei_a       = d_in[4];
    const void*  ei_b       = d_in[5];
    const float* fc1_W  = (const float*)d_in[6];
    const float* fc1_b  = (const float*)d_in[7];
    const float* fc2_W  = (const float*)d_in[8];
    const float* fc2_b  = (const float*)d_in[9];
    const float* gcn1_W = (const float*)d_in[10];
    const float* gcn1_b = (const float*)d_in[11];
    const float* gcn2_W = (const float*)d_in[12];
    const float* gcn2_b = (const float*)d_in[13];
    const float* fcc_W  = (const float*)d_in[14];
    const float* fcc_b  = (const float*)d_in[15];
    const float* out_W  = (const float*)d_in[16];
    const float* out_b  = (const float*)d_in[17];
    float* out = (float*)d_out;

    float *p_cat, *p_t, *p_comb;
    __half* p_h16;
    bf16 *whi, *wlo;
    cudaGetSymbolAddress((void**)&p_cat, g_cat);
    cudaGetSymbolAddress((void**)&p_t, g_t);
    cudaGetSymbolAddress((void**)&p_comb, g_comb);
    cudaGetSymbolAddress((void**)&p_h16, g_h16);
    cudaGetSymbolAddress((void**)&whi, g_whi);
    cudaGetSymbolAddress((void**)&wlo, g_wlo);

    cudaFuncSetAttribute(mma_gemm<1, 0>, cudaFuncAttributeMaxDynamicSharedMemorySize, SMEM_DYN);
    cudaFuncSetAttribute(mma_gemm<0, 1>, cudaFuncAttributeMaxDynamicSharedMemorySize, SMEM_DYN);

    const int GG = (NN + 63) / 64;            // 782
    const int EB = (EE + 255) / 256;
    const int NB = (NN + 255) / 256;
    const int WB = (NN * 32 + 255) / 256;

    // weight plane offsets (rows of 128): fc1 0, fc2 512, gcn1 640, gcn2 896, fcc 1024
    bf16* wfc1_hi = whi;              bf16* wfc1_lo = wlo;
    bf16* wfc2_hi = whi + 512 * 128;  bf16* wfc2_lo = wlo + 512 * 128;
    bf16* wg1_hi  = whi + 640 * 128;  bf16* wg1_lo  = wlo + 640 * 128;
    bf16* wg2_hi  = whi + 896 * 128;  bf16* wg2_lo  = wlo + 896 * 128;
    bf16* wfcc_hi = whi + 1024 * 128; bf16* wfcc_lo = wlo + 1024 * 128;

    detect_kernel<<<1, 32>>>((const unsigned int*)ei_a);
    conv_w<<<(512 * 32 + 255) / 256, 256>>>(fc1_W, wfc1_hi, wfc1_lo, 512 * 32);
    conv_w<<<(128 * 32 + 255) / 256, 256>>>(fc2_W, wfc2_hi, wfc2_lo, 128 * 32);
    conv_w<<<(256 * 32 + 255) / 256, 256>>>(gcn1_W, wg1_hi, wg1_lo, 256 * 32);
    conv_w<<<(128 * 32 + 255) / 256, 256>>>(gcn2_W, wg2_hi, wg2_lo, 128 * 32);
    conv_w<<<(512 * 32 + 255) / 256, 256>>>(fcc_W, wfcc_hi, wfcc_lo, 512 * 32);

    // MLP branches -> g_cat[:, 0:128] and [:, 128:256]
    mma_gemm<1, 0><<<GG, 256, SMEM_DYN>>>(metadata_a, 512, wfc1_hi, wfc1_lo, fc1_b, p_t, 128, nullptr, NN, 512);
    mma_gemm<1, 0><<<GG, 256, SMEM_DYN>>>(p_t, 128, wfc2_hi, wfc2_lo, fc2_b, p_cat + 0, 512, nullptr, NN, 128);
    mma_gemm<1, 0><<<GG, 256, SMEM_DYN>>>(metadata_b, 512, wfc1_hi, wfc1_lo, fc1_b, p_t, 128, nullptr, NN, 512);
    mma_gemm<1, 0><<<GG, 256, SMEM_DYN>>>(p_t, 128, wfc2_hi, wfc2_lo, fc2_b, p_cat + 128, 512, nullptr, NN, 128);

    // GCN branch, graph A -> g_cat[:, 256:384]
    zero_cnt_kernel<<<NB, 256>>>();
    degree_kernel<<<EB, 256>>>(ei_a);
    scan_kernel<<<1, 1024>>>();
    scatter_kernel<<<EB, 256>>>(ei_a);
    mma_gemm<0, 1><<<GG, 256, SMEM_DYN>>>(x_a, 256, wg1_hi, wg1_lo, nullptr, nullptr, 128, p_h16, NN, 256);
    aggregate_kernel<<<WB, 256>>>(p_h16, gcn1_b, p_t, 128);
    mma_gemm<0, 1><<<GG, 256, SMEM_DYN>>>(p_t, 128, wg2_hi, wg2_lo, nullptr, nullptr, 128, p_h16, NN, 128);
    aggregate_kernel<<<WB, 256>>>(p_h16, gcn2_b, p_cat + 256, 512);

    // GCN branch, graph B -> g_cat[:, 384:512]
    zero_cnt_kernel<<<NB, 256>>>();
    degree_kernel<<<EB, 256>>>(ei_b);
    scan_kernel<<<1, 1024>>>();
    scatter_kernel<<<EB, 256>>>(ei_b);
    mma_gemm<0, 1><<<GG, 256, SMEM_DYN>>>(x_b, 256, wg1_hi, wg1_lo, nullptr, nullptr, 128, p_h16, NN, 256);
    aggregate_kernel<<<WB, 256>>>(p_h16, gcn1_b, p_t, 128);
    mma_gemm<0, 1><<<GG, 256, SMEM_DYN>>>(p_t, 128, wg2_hi, wg2_lo, nullptr, nullptr, 128, p_h16, NN, 128);
    aggregate_kernel<<<WB, 256>>>(p_h16, gcn2_b, p_cat + 384, 512);

    // combined = relu(cat @ fcc_W + b), single K=512 GEMM
    mma_gemm<1, 0><<<GG, 256, SMEM_DYN>>>(p_cat, 512, wfcc_hi, wfcc_lo, fcc_b, p_comb, 128, nullptr, NN, 512);

    final_kernel<<<WB, 256>>>(out_W, out_b, out);
}

// round 9
// speedup vs baseline: 1.4924x; 1.1283x over previous
#include <cuda_runtime.h>
#include <cuda_bf16.h>
#include <cuda_fp16.h>
#include <cstdint>

#define NN 50000
#define EE 1600000
#define CSB 196              // scan blocks per graph: 196*256 >= 50000

typedef __nv_bfloat16 bf16;
typedef __nv_bfloat162 bf162;

// ---------------- device scratch (no allocs allowed) ----------------
__device__ __align__(256) float  g_cat[NN * 512];        // [ma | mb | ga | gb], ld=512
__device__ __align__(256) __half g_h16[2 * NN * 128];    // GCN features, both graphs
__device__ __align__(256) float  g_t2[2 * NN * 128];     // fc1 out / agg1 out, both
__device__ __align__(256) bf16   g_whi[1536 * 128];
__device__ __align__(256) bf16   g_wlo[1536 * 128];
__device__ int   g_cnt[2 * NN];
__device__ float g_dinv[2 * NN];
__device__ int   g_rowptr[2 * (NN + 1)];
__device__ int   g_cur[2 * NN];
__device__ int   g_srcidx[2 * EE];
__device__ int   g_bsum[2 * CSB];
__device__ int   g_boff[2 * CSB];
__device__ int   g_is64;

// ---------------- helpers ----------------
__device__ __forceinline__ uint32_t smem_to_u32(const void* p) {
    uint32_t a;
    asm("{ .reg .u64 t; cvta.to.shared.u64 t, %1; cvt.u32.u64 %0, t; }" : "=r"(a) : "l"(p));
    return a;
}
__device__ __forceinline__ void cpa16(uint32_t d, const void* s) {
    asm volatile("cp.async.cg.shared.global [%0], [%1], 16;" :: "r"(d), "l"(s) : "memory");
}
#define CP_COMMIT() asm volatile("cp.async.commit_group;" ::: "memory")
#define CP_WAIT1()  asm volatile("cp.async.wait_group 1;" ::: "memory")
#define CP_WAIT0()  asm volatile("cp.async.wait_group 0;" ::: "memory")

__device__ __forceinline__ void cvt_hilo(float4 v, unsigned long long& hi, unsigned long long& lo) {
    union { unsigned long long u; bf162 b[2]; } H, L;
    H.b[0] = __floats2bfloat162_rn(v.x, v.y);
    H.b[1] = __floats2bfloat162_rn(v.z, v.w);
    const float2 f0 = __bfloat1622float2(H.b[0]);
    const float2 f1 = __bfloat1622float2(H.b[1]);
    L.b[0] = __floats2bfloat162_rn(v.x - f0.x, v.y - f0.y);
    L.b[1] = __floats2bfloat162_rn(v.z - f1.x, v.w - f1.y);
    hi = H.u; lo = L.u;
}

#define LDSM_X4(d, a) \
    asm volatile("ldmatrix.sync.aligned.m8n8.x4.shared.b16 {%0,%1,%2,%3}, [%4];" \
        : "=r"((d)[0]), "=r"((d)[1]), "=r"((d)[2]), "=r"((d)[3]) : "r"(a))
#define LDSM_X4_T(d, a) \
    asm volatile("ldmatrix.sync.aligned.m8n8.x4.trans.shared.b16 {%0,%1,%2,%3}, [%4];" \
        : "=r"((d)[0]), "=r"((d)[1]), "=r"((d)[2]), "=r"((d)[3]) : "r"(a))
#define MMA_BF16(c, a, b0, b1) \
    asm volatile("mma.sync.aligned.m16n8k16.row.col.f32.bf16.bf16.f32 " \
        "{%0,%1,%2,%3}, {%4,%5,%6,%7}, {%8,%9}, {%0,%1,%2,%3};" \
        : "+f"((c)[0]), "+f"((c)[1]), "+f"((c)[2]), "+f"((c)[3]) \
        : "r"((a)[0]), "r"((a)[1]), "r"((a)[2]), "r"((a)[3]), "r"(b0), "r"(b1))

#define BUFS    27648
#define OFF_ALO 5120
#define OFF_BHI 10240
#define OFF_BLO 18944
#define SMEM_DYN (2 * BUFS)

// ---------------- HMMA split-bf16 GEMM, dual-input: C = A @ W ----------------
// OUTF: 0 = f32 (Cf0/Cf1, ldc), 1 = fp16 (Ch0/Ch1, ld=128), 2 = fused final sigmoid -> outp
template <int ACT, int OUTF>
__global__ __launch_bounds__(256, 2) void mma_gemm(
    const float* __restrict__ A0, const float* __restrict__ A1, int lda,
    const bf16* __restrict__ Whi, const bf16* __restrict__ Wlo,
    const float* __restrict__ bias,
    float* __restrict__ Cf0, float* __restrict__ Cf1, int ldc,
    __half* __restrict__ Ch0, __half* __restrict__ Ch1,
    const float* __restrict__ outW, const float* __restrict__ outb,
    float* __restrict__ outp,
    int M, int K, int halfGrid)
{
    extern __shared__ char smem[];
    const uint32_t sb = smem_to_u32(smem);
    const int tid = threadIdx.x, wid = tid >> 5, lane = tid & 31;
    const int sel = (blockIdx.x >= halfGrid) ? 1 : 0;
    const float* __restrict__ A = sel ? A1 : A0;
    const int m0 = (blockIdx.x - sel * halfGrid) * 64;
    const int m_off = (wid & 1) * 32, n_off = (wid >> 1) * 32;

    const int mi = lane >> 3, r8 = lane & 7;
    const int aRowL = m_off + (mi & 1) * 8 + r8;
    const int aColL = (mi >> 1) * 8;
    const int bRowL = (mi & 1) * 8 + r8;
    const int bColL = n_off + (mi >> 1) * 8;

    int aRow[2], aK[2];
#pragma unroll
    for (int i = 0; i < 2; i++) {
        const int f = tid * 2 + i;
        aRow[i] = f >> 3; aK[i] = (f & 7) * 4;
    }

    float acc[2][4][4];
#pragma unroll
    for (int mt = 0; mt < 2; mt++)
#pragma unroll
        for (int nt = 0; nt < 4; nt++)
#pragma unroll
            for (int j = 0; j < 4; j++) acc[mt][nt][j] = 0.f;

    float4 ra[2];
    const int nch = K >> 5;

    auto gloadA = [&](int c) {
#pragma unroll
        for (int i = 0; i < 2; i++) {
            ra[i] = make_float4(0.f, 0.f, 0.f, 0.f);
            if (m0 + aRow[i] < M)
                ra[i] = *(const float4*)(A + (size_t)(m0 + aRow[i]) * lda + c * 32 + aK[i]);
        }
    };
    auto issueB = [&](int c, int slot) {
        const uint32_t base = sb + slot * BUFS;
#pragma unroll
        for (int i = 0; i < 2; i++) {
            const int f = tid + i * 256;
            const int br = f >> 4, bq = f & 15;
            const size_t off = (size_t)(c * 32 + br) * 128 + bq * 8;
            cpa16(base + OFF_BHI + br * 272 + bq * 16, Whi + off);
            cpa16(base + OFF_BLO + br * 272 + bq * 16, Wlo + off);
        }
    };
    auto sstoreA = [&](int b) {
        char* base = smem + b * BUFS;
#pragma unroll
        for (int i = 0; i < 2; i++) {
            const uint32_t off = (uint32_t)(aRow[i] * 80 + aK[i] * 2);
            unsigned long long hi, lo;
            cvt_hilo(ra[i], hi, lo);
            *(unsigned long long*)(base + off) = hi;
            *(unsigned long long*)(base + OFF_ALO + off) = lo;
        }
    };
    auto compute = [&](int b) {
        const uint32_t aH = sb + b * BUFS;
        const uint32_t aL = aH + OFF_ALO;
        const uint32_t bH = aH + OFF_BHI;
#pragma unroll
        for (int k16 = 0; k16 < 2; k16++) {
            uint32_t ah[2][4], bh[2][4], bl[2][4];
#pragma unroll
            for (int mt = 0; mt < 2; mt++)
                LDSM_X4(ah[mt], aH + (uint32_t)(((aRowL + mt * 16) * 40 + aColL + k16 * 16) * 2));
#pragma unroll
            for (int nt = 0; nt < 2; nt++) {
                const uint32_t ba = bH +
                    (uint32_t)(((bRowL + k16 * 16) * 136 + bColL + nt * 16) * 2);
                LDSM_X4_T(bh[nt], ba);
                LDSM_X4_T(bl[nt], ba + (OFF_BLO - OFF_BHI));
            }
#pragma unroll
            for (int mt = 0; mt < 2; mt++)
#pragma unroll
                for (int nt = 0; nt < 2; nt++) {
                    MMA_BF16(acc[mt][nt * 2 + 0], ah[mt], bh[nt][0], bh[nt][1]);
                    MMA_BF16(acc[mt][nt * 2 + 1], ah[mt], bh[nt][2], bh[nt][3]);
                    MMA_BF16(acc[mt][nt * 2 + 0], ah[mt], bl[nt][0], bl[nt][1]);
                    MMA_BF16(acc[mt][nt * 2 + 1], ah[mt], bl[nt][2], bl[nt][3]);
                }
#pragma unroll
            for (int mt = 0; mt < 2; mt++)
                LDSM_X4(ah[mt], aL + (uint32_t)(((aRowL + mt * 16) * 40 + aColL + k16 * 16) * 2));
#pragma unroll
            for (int mt = 0; mt < 2; mt++)
#pragma unroll
                for (int nt = 0; nt < 2; nt++) {
                    MMA_BF16(acc[mt][nt * 2 + 0], ah[mt], bh[nt][0], bh[nt][1]);
                    MMA_BF16(acc[mt][nt * 2 + 1], ah[mt], bh[nt][2], bh[nt][3]);
                }
        }
    };

    gloadA(0);
    issueB(0, 0); CP_COMMIT();
    sstoreA(0);
    for (int c = 0; c < nch; c++) {
        if (c + 1 < nch) {
            gloadA(c + 1);
            issueB(c + 1, (c + 1) & 1); CP_COMMIT();
            CP_WAIT1();
        } else {
            CP_WAIT0();
        }
        __syncthreads();
        compute(c & 1);
        if (c + 1 < nch) {
            __syncthreads();
            sstoreA((c + 1) & 1);
        }
    }

    // ---------------- epilogue ----------------
    const int er = lane >> 2, ec = (lane & 3) * 2;
    if (OUTF == 2) {
        float* red = (float*)smem;
        __syncthreads();                 // mainloop smem reads complete before reuse
        if (tid < 64) red[tid] = 0.f;
        __syncthreads();
#pragma unroll
        for (int mt = 0; mt < 2; mt++) {
            float s0 = 0.f, s1 = 0.f;
#pragma unroll
            for (int nt = 0; nt < 4; nt++) {
                const int col = n_off + nt * 8 + ec;
                const float b0 = __ldg(&bias[col]), b1 = __ldg(&bias[col + 1]);
                const float w0 = __ldg(&outW[col]), w1 = __ldg(&outW[col + 1]);
                s0 += fmaxf(acc[mt][nt][0] + b0, 0.f) * w0 + fmaxf(acc[mt][nt][1] + b1, 0.f) * w1;
                s1 += fmaxf(acc[mt][nt][2] + b0, 0.f) * w0 + fmaxf(acc[mt][nt][3] + b1, 0.f) * w1;
            }
            atomicAdd(&red[m_off + mt * 16 + er], s0);
            atomicAdd(&red[m_off + mt * 16 + er + 8], s1);
        }
        __syncthreads();
        if (tid < 64 && m0 + tid < M)
            outp[m0 + tid] = 1.0f / (1.0f + expf(-(red[tid] + __ldg(outb))));
        return;
    }
#pragma unroll
    for (int mt = 0; mt < 2; mt++) {
        const int row0 = m0 + m_off + mt * 16 + er;
#pragma unroll
        for (int nt = 0; nt < 4; nt++) {
            const int col = n_off + nt * 8 + ec;
            float b0 = 0.f, b1 = 0.f;
            if (bias) { b0 = __ldg(&bias[col]); b1 = __ldg(&bias[col + 1]); }
            float v0 = acc[mt][nt][0] + b0, v1 = acc[mt][nt][1] + b1;
            float v2 = acc[mt][nt][2] + b0, v3 = acc[mt][nt][3] + b1;
            if (ACT) {
                v0 = fmaxf(v0, 0.f); v1 = fmaxf(v1, 0.f);
                v2 = fmaxf(v2, 0.f); v3 = fmaxf(v3, 0.f);
            }
            if (OUTF == 0) {
                float* Cf = sel ? Cf1 : Cf0;
                if (row0 < M) *(float2*)(Cf + (size_t)row0 * ldc + col) = make_float2(v0, v1);
                if (row0 + 8 < M) *(float2*)(Cf + (size_t)(row0 + 8) * ldc + col) = make_float2(v2, v3);
            } else {
                __half* Ch = sel ? Ch1 : Ch0;
                if (row0 < M)
                    *(__half2*)(Ch + (size_t)row0 * 128 + col) = __floats2half2_rn(v0, v1);
                if (row0 + 8 < M)
                    *(__half2*)(Ch + (size_t)(row0 + 8) * 128 + col) = __floats2half2_rn(v2, v3);
            }
        }
    }
}

// ---------------- merged weight conversion ----------------
__global__ void conv_w_all(const float* __restrict__ w0, const float* __restrict__ w1,
                           const float* __restrict__ w2, const float* __restrict__ w3,
                           const float* __restrict__ w4)
{
    const int i = blockIdx.x * blockDim.x + threadIdx.x;   // float4 index, 49152 total
    if (i >= 49152) return;
    const float* src; int rel, dst;
    if (i < 16384)      { src = w0; rel = i;         dst = 0;            }
    else if (i < 20480) { src = w1; rel = i - 16384; dst = 512 * 32;     }
    else if (i < 28672) { src = w2; rel = i - 20480; dst = 640 * 32;     }
    else if (i < 32768) { src = w3; rel = i - 28672; dst = 896 * 32;     }
    else                { src = w4; rel = i - 32768; dst = 1024 * 32;    }
    const float4 v = ((const float4*)src)[rel];
    unsigned long long h, l;
    cvt_hilo(v, h, l);
    ((unsigned long long*)g_whi)[dst + rel] = h;
    ((unsigned long long*)g_wlo)[dst + rel] = l;
}

// ---------------- edge-index dtype detection ----------------
__global__ void detect_kernel(const unsigned int* __restrict__ w) {
    if (threadIdx.x == 0 && blockIdx.x == 0) {
        int zeros = 0;
        for (int i = 1; i < 512; i += 2) zeros += (w[i] == 0u) ? 1 : 0;
        g_is64 = (zeros >= 200) ? 1 : 0;
    }
}
__device__ __forceinline__ int load_idx(const void* ei, long long pos, int is64) {
    if (is64) return (int)((const long long*)ei)[pos];
    return ((const int*)ei)[pos];
}

// ---------------- CSR build (both graphs per launch) ----------------
__global__ void zero_cnt_kernel() {
    const int i = blockIdx.x * blockDim.x + threadIdx.x;
    if (i < 2 * NN) g_cnt[i] = 0;
}
__global__ void degree_kernel(const void* __restrict__ eia, const void* __restrict__ eib) {
    const int i = blockIdx.x * blockDim.x + threadIdx.x;
    if (i < 2 * EE) {
        const int g = (i >= EE) ? 1 : 0;
        const void* ei = g ? eib : eia;
        const int e = i - g * EE;
        const int dst = load_idx(ei, (long long)EE + e, g_is64);
        if ((unsigned)dst < NN) atomicAdd(&g_cnt[g * NN + dst], 1);
    }
}
// stage 1: per-block exclusive scan + block sums
__global__ void scan1_kernel() {
    __shared__ int wsum[8];
    const int g = (blockIdx.x >= CSB) ? 1 : 0;
    const int b = blockIdx.x - g * CSB;
    const int t = threadIdx.x, lane = t & 31, wd = t >> 5;
    const int idx = b * 256 + t;
    const int v = (idx < NN) ? g_cnt[g * NN + idx] : 0;
    int x = v;
#pragma unroll
    for (int off = 1; off < 32; off <<= 1) {
        const int y = __shfl_up_sync(0xffffffffu, x, off);
        if (lane >= off) x += y;
    }
    if (lane == 31) wsum[wd] = x;
    __syncthreads();
    if (t < 8) {
        int s = wsum[t];
#pragma unroll
        for (int off = 1; off < 8; off <<= 1) {
            const int y = __shfl_up_sync(0xffu, s, off);
            if (t >= off) s += y;
        }
        wsum[t] = s;
    }
    __syncthreads();
    const int excl = (wd ? wsum[wd - 1] : 0) + x - v;
    if (idx < NN) g_rowptr[g * (NN + 1) + idx] = excl;
    if (t == 255) g_bsum[g * CSB + b] = excl + v;
}
// stage 2: scan block sums (one warp per graph)
__global__ void scan2_kernel() {
    const int t = threadIdx.x, lane = t & 31, g = t >> 5;
    if (g >= 2) return;
    int carry = 0;
    for (int base = 0; base < CSB; base += 32) {
        const int i = base + lane;
        const int v = (i < CSB) ? g_bsum[g * CSB + i] : 0;
        int x = v;
#pragma unroll
        for (int off = 1; off < 32; off <<= 1) {
            const int y = __shfl_up_sync(0xffffffffu, x, off);
            if (lane >= off) x += y;
        }
        if (i < CSB) g_boff[g * CSB + i] = carry + x - v;
        carry += __shfl_sync(0xffffffffu, x, 31);
    }
    if (lane == 0) g_rowptr[g * (NN + 1) + NN] = carry;
}
// stage 3: add block offsets, init cursors + dinv
__global__ void scan3_kernel() {
    const int i = blockIdx.x * blockDim.x + threadIdx.x;
    if (i >= 2 * NN) return;
    const int g = (i >= NN) ? 1 : 0;
    const int ln = i - g * NN;
    const int rp = g_rowptr[g * (NN + 1) + ln] + g_boff[g * CSB + ln / 256];
    g_rowptr[g * (NN + 1) + ln] = rp;
    g_cur[i] = rp;
    g_dinv[i] = rsqrtf((float)g_cnt[i] + 1.0f);
}
__global__ void scatter_kernel(const void* __restrict__ eia, const void* __restrict__ eib) {
    const int i = blockIdx.x * blockDim.x + threadIdx.x;
    if (i < 2 * EE) {
        const int g = (i >= EE) ? 1 : 0;
        const void* ei = g ? eib : eia;
        const int e = i - g * EE;
        const int is64 = g_is64;
        const int dst = load_idx(ei, (long long)EE + e, is64);
        const int src = load_idx(ei, (long long)e, is64);
        if ((unsigned)dst < NN && (unsigned)src < NN) {
            const int pos = atomicAdd(&g_cur[g * NN + dst], 1);
            if ((unsigned)pos < EE) g_srcidx[(size_t)g * EE + pos] = src;
        }
    }
}

// ---------------- GCN aggregation, both graphs: fp16 gather, f32 out ----------------
__global__ __launch_bounds__(256) void aggregate_kernel(
    const __half* __restrict__ H, const float* __restrict__ bias,
    float* __restrict__ out, int ldo, long long goff)
{
    const int gt = blockIdx.x * blockDim.x + threadIdx.x;
    const int node = gt >> 5, lane = gt & 31;
    if (node >= 2 * NN) return;
    const int g = (node >= NN) ? 1 : 0;
    const int ln = node - g * NN;
    const int* __restrict__ rp = g_rowptr + g * (NN + 1);
    const float* __restrict__ dv = g_dinv + g * NN;
    const int* __restrict__ si = g_srcidx + (size_t)g * EE;
    const __half* __restrict__ Hg = H + (size_t)g * NN * 128;

    const float di = dv[ln];
    float acc[4];
    {
        const float w = di * di;
        const uint2 v = *(const uint2*)(Hg + (size_t)ln * 128 + lane * 4);
        const float2 f0 = __half22float2(*(const __half2*)&v.x);
        const float2 f1 = __half22float2(*(const __half2*)&v.y);
        acc[0] = f0.x * w; acc[1] = f0.y * w; acc[2] = f1.x * w; acc[3] = f1.y * w;
    }
    const int beg = rp[ln], end = rp[ln + 1];
    for (int e = beg; e < end; e++) {
        const int s = __ldg(&si[e]);
        const float w = di * __ldg(&dv[s]);
        const uint2 v = *(const uint2*)(Hg + (size_t)s * 128 + lane * 4);
        const float2 f0 = __half22float2(*(const __half2*)&v.x);
        const float2 f1 = __half22float2(*(const __half2*)&v.y);
        acc[0] = fmaf(f0.x, w, acc[0]);
        acc[1] = fmaf(f0.y, w, acc[1]);
        acc[2] = fmaf(f1.x, w, acc[2]);
        acc[3] = fmaf(f1.y, w, acc[3]);
    }
    const float4 b = *(const float4*)(bias + lane * 4);
    *(float4*)(out + (size_t)g * goff + (size_t)ln * ldo + lane * 4) =
        make_float4(fmaxf(acc[0] + b.x, 0.f), fmaxf(acc[1] + b.y, 0.f),
                    fmaxf(acc[2] + b.z, 0.f), fmaxf(acc[3] + b.w, 0.f));
}

// ---------------- orchestration ----------------
extern "C" void kernel_launch(void* const* d_in, const int* in_sizes, int n_in,
                              void* d_out, int out_size)
{
    const float* metadata_a = (const float*)d_in[0];
    const float* metadata_b = (const float*)d_in[1];
    const float* x_a        = (const float*)d_in[2];
    const float* x_b        = (const float*)d_in[3];
    const void*  ei_a       = d_in[4];
    const void*  ei_b       = d_in[5];
    const float* fc1_W  = (const float*)d_in[6];
    const float* fc1_b  = (const float*)d_in[7];
    const float* fc2_W  = (const float*)d_in[8];
    const float* fc2_b  = (const float*)d_in[9];
    const float* gcn1_W = (const float*)d_in[10];
    const float* gcn1_b = (const float*)d_in[11];
    const float* gcn2_W = (const float*)d_in[12];
    const float* gcn2_b = (const float*)d_in[13];
    const float* fcc_W  = (const float*)d_in[14];
    const float* fcc_b  = (const float*)d_in[15];
    const float* out_W  = (const float*)d_in[16];
    const float* out_b  = (const float*)d_in[17];
    float* out = (float*)d_out;

    float *p_cat, *p_t2;
    __half* p_h16;
    bf16 *whi, *wlo;
    cudaGetSymbolAddress((void**)&p_cat, g_cat);
    cudaGetSymbolAddress((void**)&p_t2, g_t2);
    cudaGetSymbolAddress((void**)&p_h16, g_h16);
    cudaGetSymbolAddress((void**)&whi, g_whi);
    cudaGetSymbolAddress((void**)&wlo, g_wlo);

    cudaFuncSetAttribute(mma_gemm<1, 0>, cudaFuncAttributeMaxDynamicSharedMemorySize, SMEM_DYN);
    cudaFuncSetAttribute(mma_gemm<0, 1>, cudaFuncAttributeMaxDynamicSharedMemorySize, SMEM_DYN);
    cudaFuncSetAttribute(mma_gemm<1, 2>, cudaFuncAttributeMaxDynamicSharedMemorySize, SMEM_DYN);

    const int GG = (NN + 63) / 64;                 // 782 per half
    const int E2 = (2 * EE + 255) / 256;
    const int N2 = (2 * NN + 255) / 256;
    const int WB2 = (2 * NN * 32 + 255) / 256;

    bf16* wfc1_hi = whi;              bf16* wfc1_lo = wlo;
    bf16* wfc2_hi = whi + 512 * 128;  bf16* wfc2_lo = wlo + 512 * 128;
    bf16* wg1_hi  = whi + 640 * 128;  bf16* wg1_lo  = wlo + 640 * 128;
    bf16* wg2_hi  = whi + 896 * 128;  bf16* wg2_lo  = wlo + 896 * 128;
    bf16* wfcc_hi = whi + 1024 * 128; bf16* wfcc_lo = wlo + 1024 * 128;

    detect_kernel<<<1, 32>>>((const unsigned int*)ei_a);
    conv_w_all<<<(49152 + 255) / 256, 256>>>(fc1_W, fc2_W, gcn1_W, gcn2_W, fcc_W);

    // CSR build, both graphs
    zero_cnt_kernel<<<N2, 256>>>();
    degree_kernel<<<E2, 256>>>(ei_a, ei_b);
    scan1_kernel<<<2 * CSB, 256>>>();
    scan2_kernel<<<1, 64>>>();
    scan3_kernel<<<N2, 256>>>();
    scatter_kernel<<<E2, 256>>>(ei_a, ei_b);

    // MLP branches (dual) -> cat[:, 0:128] / [:, 128:256]
    mma_gemm<1, 0><<<2 * GG, 256, SMEM_DYN>>>(metadata_a, metadata_b, 512, wfc1_hi, wfc1_lo, fc1_b,
        p_t2, p_t2 + (size_t)NN * 128, 128, nullptr, nullptr, nullptr, nullptr, nullptr, NN, 512, GG);
    mma_gemm<1, 0><<<2 * GG, 256, SMEM_DYN>>>(p_t2, p_t2 + (size_t)NN * 128, 128, wfc2_hi, wfc2_lo, fc2_b,
        p_cat + 0, p_cat + 128, 512, nullptr, nullptr, nullptr, nullptr, nullptr, NN, 128, GG);

    // GCN layer 1 (dual): XW -> h16, aggregate -> t2
    mma_gemm<0, 1><<<2 * GG, 256, SMEM_DYN>>>(x_a, x_b, 256, wg1_hi, wg1_lo, nullptr,
        nullptr, nullptr, 0, p_h16, p_h16 + (size_t)NN * 128, nullptr, nullptr, nullptr, NN, 256, GG);
    aggregate_kernel<<<WB2, 256>>>(p_h16, gcn1_b, p_t2, 128, (long long)NN * 128);

    // GCN layer 2 (dual): XW -> h16, aggregate -> cat[:, 256:384] / [:, 384:512]
    mma_gemm<0, 1><<<2 * GG, 256, SMEM_DYN>>>(p_t2, p_t2 + (size_t)NN * 128, 128, wg2_hi, wg2_lo, nullptr,
        nullptr, nullptr, 0, p_h16, p_h16 + (size_t)NN * 128, nullptr, nullptr, nullptr, NN, 128, GG);
    aggregate_kernel<<<WB2, 256>>>(p_h16, gcn2_b, p_cat + 256, 512, 128LL);

    // fused: out = sigmoid(relu(cat @ fccW + fccb) @ outW + outb)
    mma_gemm<1, 2><<<GG, 256, SMEM_DYN>>>(p_cat, p_cat, 512, wfcc_hi, wfcc_lo, fcc_b,
        nullptr, nullptr, 0, nullptr, nullptr, out_W, out_b, out, NN, 512, GG);
}

// round 10
// speedup vs baseline: 1.9539x; 1.3092x over previous
#include <cuda_runtime.h>
#include <cuda_bf16.h>
#include <cuda_fp16.h>
#include <cstdint>

#define NN 50000
#define EE 1600000
#define CSB 196              // scan blocks per graph: 196*256 >= 50000

// ---------------- device scratch (no allocs allowed) ----------------
__device__ __align__(256) float  g_cat[NN * 512];        // [ma | mb | ga | gb], ld=512
__device__ __align__(256) __half g_h16[2 * NN * 128];    // GCN features, both graphs
__device__ __align__(256) float  g_t2[2 * NN * 128];     // fc1 out / agg1 out, both
__device__ __align__(256) __half g_wh[1536 * 128];       // fp16 weight planes
__device__ int   g_cnt[2 * NN];
__device__ float g_dinv[2 * NN];
__device__ int   g_rowptr[2 * (NN + 1)];
__device__ int   g_cur[2 * NN];
__device__ int   g_srcidx[2 * EE];
__device__ int   g_bsum[2 * CSB];
__device__ int   g_boff[2 * CSB];
__device__ int   g_is64;

// ---------------- helpers ----------------
__device__ __forceinline__ uint32_t smem_to_u32(const void* p) {
    uint32_t a;
    asm("{ .reg .u64 t; cvta.to.shared.u64 t, %1; cvt.u32.u64 %0, t; }" : "=r"(a) : "l"(p));
    return a;
}
__device__ __forceinline__ void cpa16(uint32_t d, const void* s) {
    asm volatile("cp.async.cg.shared.global [%0], [%1], 16;" :: "r"(d), "l"(s) : "memory");
}
#define CP_COMMIT() asm volatile("cp.async.commit_group;" ::: "memory")
#define CP_WAIT1()  asm volatile("cp.async.wait_group 1;" ::: "memory")
#define CP_WAIT0()  asm volatile("cp.async.wait_group 0;" ::: "memory")

__device__ __forceinline__ unsigned long long pack4h(float4 v) {
    union { unsigned long long u; __half2 h[2]; } P;
    P.h[0] = __floats2half2_rn(v.x, v.y);
    P.h[1] = __floats2half2_rn(v.z, v.w);
    return P.u;
}

#define LDSM_X4(d, a) \
    asm volatile("ldmatrix.sync.aligned.m8n8.x4.shared.b16 {%0,%1,%2,%3}, [%4];" \
        : "=r"((d)[0]), "=r"((d)[1]), "=r"((d)[2]), "=r"((d)[3]) : "r"(a))
#define LDSM_X4_T(d, a) \
    asm volatile("ldmatrix.sync.aligned.m8n8.x4.trans.shared.b16 {%0,%1,%2,%3}, [%4];" \
        : "=r"((d)[0]), "=r"((d)[1]), "=r"((d)[2]), "=r"((d)[3]) : "r"(a))
#define MMA_F16(c, a, b0, b1) \
    asm volatile("mma.sync.aligned.m16n8k16.row.col.f32.f16.f16.f32 " \
        "{%0,%1,%2,%3}, {%4,%5,%6,%7}, {%8,%9}, {%0,%1,%2,%3};" \
        : "+f"((c)[0]), "+f"((c)[1]), "+f"((c)[2]), "+f"((c)[3]) \
        : "r"((a)[0]), "r"((a)[1]), "r"((a)[2]), "r"((a)[3]), "r"(b0), "r"(b1))

// per buffer: A 64x(32+8pad)fp16 = 5120B | B 32x(128+8)fp16 = 8704B
#define BUFS   13824
#define OFF_B  5120
#define SMEM_DYN (2 * BUFS)

// ---------------- HMMA fp16 GEMM, dual-input: C = A @ W ----------------
// OUTF: 0 = f32 (Cf0/Cf1, ldc), 1 = fp16 (Ch0/Ch1, ld=128), 2 = fused final sigmoid -> outp
template <int ACT, int OUTF>
__global__ __launch_bounds__(256, 2) void mma_gemm(
    const float* __restrict__ A0, const float* __restrict__ A1, int lda,
    const __half* __restrict__ Wh,
    const float* __restrict__ bias,
    float* __restrict__ Cf0, float* __restrict__ Cf1, int ldc,
    __half* __restrict__ Ch0, __half* __restrict__ Ch1,
    const float* __restrict__ outW, const float* __restrict__ outb,
    float* __restrict__ outp,
    int M, int K, int halfGrid)
{
    extern __shared__ char smem[];
    const uint32_t sb = smem_to_u32(smem);
    const int tid = threadIdx.x, wid = tid >> 5, lane = tid & 31;
    const int sel = (blockIdx.x >= halfGrid) ? 1 : 0;
    const float* __restrict__ A = sel ? A1 : A0;
    const int m0 = (blockIdx.x - sel * halfGrid) * 64;
    const int m_off = (wid & 1) * 32, n_off = (wid >> 1) * 32;

    const int mi = lane >> 3, r8 = lane & 7;
    const int aRowL = m_off + (mi & 1) * 8 + r8;
    const int aColL = (mi >> 1) * 8;
    const int bRowL = (mi & 1) * 8 + r8;
    const int bColL = n_off + (mi >> 1) * 8;

    int aRow[2], aK[2];
#pragma unroll
    for (int i = 0; i < 2; i++) {
        const int f = tid * 2 + i;
        aRow[i] = f >> 3; aK[i] = (f & 7) * 4;
    }

    float acc[2][4][4];
#pragma unroll
    for (int mt = 0; mt < 2; mt++)
#pragma unroll
        for (int nt = 0; nt < 4; nt++)
#pragma unroll
            for (int j = 0; j < 4; j++) acc[mt][nt][j] = 0.f;

    float4 ra[2];
    const int nch = K >> 5;

    auto gloadA = [&](int c) {
#pragma unroll
        for (int i = 0; i < 2; i++) {
            ra[i] = make_float4(0.f, 0.f, 0.f, 0.f);
            if (m0 + aRow[i] < M)
                ra[i] = *(const float4*)(A + (size_t)(m0 + aRow[i]) * lda + c * 32 + aK[i]);
        }
    };
    auto issueB = [&](int c, int slot) {
        const uint32_t base = sb + slot * BUFS + OFF_B;
#pragma unroll
        for (int i = 0; i < 2; i++) {
            const int f = tid + i * 256;
            const int br = f >> 4, bq = f & 15;
            cpa16(base + br * 272 + bq * 16, Wh + (size_t)(c * 32 + br) * 128 + bq * 8);
        }
    };
    auto sstoreA = [&](int b) {
        char* base = smem + b * BUFS;
#pragma unroll
        for (int i = 0; i < 2; i++)
            *(unsigned long long*)(base + aRow[i] * 80 + aK[i] * 2) = pack4h(ra[i]);
    };
    auto compute = [&](int b) {
        const uint32_t aB = sb + b * BUFS;
        const uint32_t bB = aB + OFF_B;
#pragma unroll
        for (int k16 = 0; k16 < 2; k16++) {
            uint32_t ah[2][4], bh[2][4];
#pragma unroll
            for (int mt = 0; mt < 2; mt++)
                LDSM_X4(ah[mt], aB + (uint32_t)(((aRowL + mt * 16) * 40 + aColL + k16 * 16) * 2));
#pragma unroll
            for (int nt = 0; nt < 2; nt++)
                LDSM_X4_T(bh[nt], bB + (uint32_t)(((bRowL + k16 * 16) * 136 + bColL + nt * 16) * 2));
#pragma unroll
            for (int mt = 0; mt < 2; mt++)
#pragma unroll
                for (int nt = 0; nt < 2; nt++) {
                    MMA_F16(acc[mt][nt * 2 + 0], ah[mt], bh[nt][0], bh[nt][1]);
                    MMA_F16(acc[mt][nt * 2 + 1], ah[mt], bh[nt][2], bh[nt][3]);
                }
        }
    };

    gloadA(0);
    issueB(0, 0); CP_COMMIT();
    sstoreA(0);
    for (int c = 0; c < nch; c++) {
        if (c + 1 < nch) {
            gloadA(c + 1);
            issueB(c + 1, (c + 1) & 1); CP_COMMIT();
            CP_WAIT1();
        } else {
            CP_WAIT0();
        }
        __syncthreads();
        compute(c & 1);
        if (c + 1 < nch) {
            __syncthreads();
            sstoreA((c + 1) & 1);
        }
    }

    // ---------------- epilogue ----------------
    const int er = lane >> 2, ec = (lane & 3) * 2;
    if (OUTF == 2) {
        float* red = (float*)smem;
        __syncthreads();
        if (tid < 64) red[tid] = 0.f;
        __syncthreads();
#pragma unroll
        for (int mt = 0; mt < 2; mt++) {
            float s0 = 0.f, s1 = 0.f;
#pragma unroll
            for (int nt = 0; nt < 4; nt++) {
                const int col = n_off + nt * 8 + ec;
                const float b0 = __ldg(&bias[col]), b1 = __ldg(&bias[col + 1]);
                const float w0 = __ldg(&outW[col]), w1 = __ldg(&outW[col + 1]);
                s0 += fmaxf(acc[mt][nt][0] + b0, 0.f) * w0 + fmaxf(acc[mt][nt][1] + b1, 0.f) * w1;
                s1 += fmaxf(acc[mt][nt][2] + b0, 0.f) * w0 + fmaxf(acc[mt][nt][3] + b1, 0.f) * w1;
            }
            atomicAdd(&red[m_off + mt * 16 + er], s0);
            atomicAdd(&red[m_off + mt * 16 + er + 8], s1);
        }
        __syncthreads();
        if (tid < 64 && m0 + tid < M)
            outp[m0 + tid] = 1.0f / (1.0f + expf(-(red[tid] + __ldg(outb))));
        return;
    }
#pragma unroll
    for (int mt = 0; mt < 2; mt++) {
        const int row0 = m0 + m_off + mt * 16 + er;
#pragma unroll
        for (int nt = 0; nt < 4; nt++) {
            const int col = n_off + nt * 8 + ec;
            float b0 = 0.f, b1 = 0.f;
            if (bias) { b0 = __ldg(&bias[col]); b1 = __ldg(&bias[col + 1]); }
            float v0 = acc[mt][nt][0] + b0, v1 = acc[mt][nt][1] + b1;
            float v2 = acc[mt][nt][2] + b0, v3 = acc[mt][nt][3] + b1;
            if (ACT) {
                v0 = fmaxf(v0, 0.f); v1 = fmaxf(v1, 0.f);
                v2 = fmaxf(v2, 0.f); v3 = fmaxf(v3, 0.f);
            }
            if (OUTF == 0) {
                float* Cf = sel ? Cf1 : Cf0;
                if (row0 < M) *(float2*)(Cf + (size_t)row0 * ldc + col) = make_float2(v0, v1);
                if (row0 + 8 < M) *(float2*)(Cf + (size_t)(row0 + 8) * ldc + col) = make_float2(v2, v3);
            } else {
                __half* Ch = sel ? Ch1 : Ch0;
                if (row0 < M)
                    *(__half2*)(Ch + (size_t)row0 * 128 + col) = __floats2half2_rn(v0, v1);
                if (row0 + 8 < M)
                    *(__half2*)(Ch + (size_t)(row0 + 8) * 128 + col) = __floats2half2_rn(v2, v3);
            }
        }
    }
}

// ---------------- merged weight conversion (f32 -> fp16 plane) ----------------
__global__ void conv_w_all(const float* __restrict__ w0, const float* __restrict__ w1,
                           const float* __restrict__ w2, const float* __restrict__ w3,
                           const float* __restrict__ w4)
{
    const int i = blockIdx.x * blockDim.x + threadIdx.x;   // float4 index, 49152 total
    if (i >= 49152) return;
    const float* src; int rel, dst;
    if (i < 16384)      { src = w0; rel = i;         dst = 0;         }
    else if (i < 20480) { src = w1; rel = i - 16384; dst = 512 * 32;  }
    else if (i < 28672) { src = w2; rel = i - 20480; dst = 640 * 32;  }
    else if (i < 32768) { src = w3; rel = i - 28672; dst = 896 * 32;  }
    else                { src = w4; rel = i - 32768; dst = 1024 * 32; }
    ((unsigned long long*)g_wh)[dst + rel] = pack4h(((const float4*)src)[rel]);
}

// ---------------- edge-index dtype detection ----------------
__global__ void detect_kernel(const unsigned int* __restrict__ w) {
    if (threadIdx.x == 0 && blockIdx.x == 0) {
        int zeros = 0;
        for (int i = 1; i < 512; i += 2) zeros += (w[i] == 0u) ? 1 : 0;
        g_is64 = (zeros >= 200) ? 1 : 0;
    }
}
__device__ __forceinline__ int load_idx(const void* ei, long long pos, int is64) {
    if (is64) return (int)((const long long*)ei)[pos];
    return ((const int*)ei)[pos];
}

// ---------------- CSR build (both graphs per launch) ----------------
__global__ void zero_cnt_kernel() {
    const int i = blockIdx.x * blockDim.x + threadIdx.x;
    if (i < 2 * NN) g_cnt[i] = 0;
}
__global__ void degree_kernel(const void* __restrict__ eia, const void* __restrict__ eib) {
    const int i = blockIdx.x * blockDim.x + threadIdx.x;
    if (i < 2 * EE) {
        const int g = (i >= EE) ? 1 : 0;
        const void* ei = g ? eib : eia;
        const int e = i - g * EE;
        const int dst = load_idx(ei, (long long)EE + e, g_is64);
        if ((unsigned)dst < NN) atomicAdd(&g_cnt[g * NN + dst], 1);
    }
}
__global__ void scan1_kernel() {
    __shared__ int wsum[8];
    const int g = (blockIdx.x >= CSB) ? 1 : 0;
    const int b = blockIdx.x - g * CSB;
    const int t = threadIdx.x, lane = t & 31, wd = t >> 5;
    const int idx = b * 256 + t;
    const int v = (idx < NN) ? g_cnt[g * NN + idx] : 0;
    int x = v;
#pragma unroll
    for (int off = 1; off < 32; off <<= 1) {
        const int y = __shfl_up_sync(0xffffffffu, x, off);
        if (lane >= off) x += y;
    }
    if (lane == 31) wsum[wd] = x;
    __syncthreads();
    if (t < 8) {
        int s = wsum[t];
#pragma unroll
        for (int off = 1; off < 8; off <<= 1) {
            const int y = __shfl_up_sync(0xffu, s, off);
            if (t >= off) s += y;
        }
        wsum[t] = s;
    }
    __syncthreads();
    const int excl = (wd ? wsum[wd - 1] : 0) + x - v;
    if (idx < NN) g_rowptr[g * (NN + 1) + idx] = excl;
    if (t == 255) g_bsum[g * CSB + b] = excl + v;
}
__global__ void scan2_kernel() {
    const int t = threadIdx.x, lane = t & 31, g = t >> 5;
    if (g >= 2) return;
    int carry = 0;
    for (int base = 0; base < CSB; base += 32) {
        const int i = base + lane;
        const int v = (i < CSB) ? g_bsum[g * CSB + i] : 0;
        int x = v;
#pragma unroll
        for (int off = 1; off < 32; off <<= 1) {
            const int y = __shfl_up_sync(0xffffffffu, x, off);
            if (lane >= off) x += y;
        }
        if (i < CSB) g_boff[g * CSB + i] = carry + x - v;
        carry += __shfl_sync(0xffffffffu, x, 31);
    }
    if (lane == 0) g_rowptr[g * (NN + 1) + NN] = carry;
}
__global__ void scan3_kernel() {
    const int i = blockIdx.x * blockDim.x + threadIdx.x;
    if (i >= 2 * NN) return;
    const int g = (i >= NN) ? 1 : 0;
    const int ln = i - g * NN;
    const int rp = g_rowptr[g * (NN + 1) + ln] + g_boff[g * CSB + ln / 256];
    g_rowptr[g * (NN + 1) + ln] = rp;
    g_cur[i] = rp;
    g_dinv[i] = rsqrtf((float)g_cnt[i] + 1.0f);
}
__global__ void scatter_kernel(const void* __restrict__ eia, const void* __restrict__ eib) {
    const int i = blockIdx.x * blockDim.x + threadIdx.x;
    if (i < 2 * EE) {
        const int g = (i >= EE) ? 1 : 0;
        const void* ei = g ? eib : eia;
        const int e = i - g * EE;
        const int is64 = g_is64;
        const int dst = load_idx(ei, (long long)EE + e, is64);
        const int src = load_idx(ei, (long long)e, is64);
        if ((unsigned)dst < NN && (unsigned)src < NN) {
            const int pos = atomicAdd(&g_cur[g * NN + dst], 1);
            if ((unsigned)pos < EE) g_srcidx[(size_t)g * EE + pos] = src;
        }
    }
}

// ---------------- GCN aggregation, both graphs: fp16 gather, f32 out ----------------
__global__ __launch_bounds__(256) void aggregate_kernel(
    const __half* __restrict__ H, const float* __restrict__ bias,
    float* __restrict__ out, int ldo, long long goff)
{
    const int gt = blockIdx.x * blockDim.x + threadIdx.x;
    const int node = gt >> 5, lane = gt & 31;
    if (node >= 2 * NN) return;
    const int g = (node >= NN) ? 1 : 0;
    const int ln = node - g * NN;
    const int* __restrict__ rp = g_rowptr + g * (NN + 1);
    const float* __restrict__ dv = g_dinv + g * NN;
    const int* __restrict__ si = g_srcidx + (size_t)g * EE;
    const __half* __restrict__ Hg = H + (size_t)g * NN * 128;

    const float di = dv[ln];
    float acc[4];
    {
        const float w = di * di;
        const uint2 v = *(const uint2*)(Hg + (size_t)ln * 128 + lane * 4);
        const float2 f0 = __half22float2(*(const __half2*)&v.x);
        const float2 f1 = __half22float2(*(const __half2*)&v.y);
        acc[0] = f0.x * w; acc[1] = f0.y * w; acc[2] = f1.x * w; acc[3] = f1.y * w;
    }
    const int beg = rp[ln], end = rp[ln + 1];
    for (int e = beg; e < end; e++) {
        const int s = __ldg(&si[e]);
        const float w = di * __ldg(&dv[s]);
        const uint2 v = *(const uint2*)(Hg + (size_t)s * 128 + lane * 4);
        const float2 f0 = __half22float2(*(const __half2*)&v.x);
        const float2 f1 = __half22float2(*(const __half2*)&v.y);
        acc[0] = fmaf(f0.x, w, acc[0]);
        acc[1] = fmaf(f0.y, w, acc[1]);
        acc[2] = fmaf(f1.x, w, acc[2]);
        acc[3] = fmaf(f1.y, w, acc[3]);
    }
    const float4 b = *(const float4*)(bias + lane * 4);
    *(float4*)(out + (size_t)g * goff + (size_t)ln * ldo + lane * 4) =
        make_float4(fmaxf(acc[0] + b.x, 0.f), fmaxf(acc[1] + b.y, 0.f),
                    fmaxf(acc[2] + b.z, 0.f), fmaxf(acc[3] + b.w, 0.f));
}

// ---------------- orchestration ----------------
extern "C" void kernel_launch(void* const* d_in, const int* in_sizes, int n_in,
                              void* d_out, int out_size)
{
    const float* metadata_a = (const float*)d_in[0];
    const float* metadata_b = (const float*)d_in[1];
    const float* x_a        = (const float*)d_in[2];
    const float* x_b        = (const float*)d_in[3];
    const void*  ei_a       = d_in[4];
    const void*  ei_b       = d_in[5];
    const float* fc1_W  = (const float*)d_in[6];
    const float* fc1_b  = (const float*)d_in[7];
    const float* fc2_W  = (const float*)d_in[8];
    const float* fc2_b  = (const float*)d_in[9];
    const float* gcn1_W = (const float*)d_in[10];
    const float* gcn1_b = (const float*)d_in[11];
    const float* gcn2_W = (const float*)d_in[12];
    const float* gcn2_b = (const float*)d_in[13];
    const float* fcc_W  = (const float*)d_in[14];
    const float* fcc_b  = (const float*)d_in[15];
    const float* out_W  = (const float*)d_in[16];
    const float* out_b  = (const float*)d_in[17];
    float* out = (float*)d_out;

    float *p_cat, *p_t2;
    __half *p_h16, *wh;
    cudaGetSymbolAddress((void**)&p_cat, g_cat);
    cudaGetSymbolAddress((void**)&p_t2, g_t2);
    cudaGetSymbolAddress((void**)&p_h16, g_h16);
    cudaGetSymbolAddress((void**)&wh, g_wh);

    cudaFuncSetAttribute(mma_gemm<1, 0>, cudaFuncAttributeMaxDynamicSharedMemorySize, SMEM_DYN);
    cudaFuncSetAttribute(mma_gemm<0, 1>, cudaFuncAttributeMaxDynamicSharedMemorySize, SMEM_DYN);
    cudaFuncSetAttribute(mma_gemm<1, 2>, cudaFuncAttributeMaxDynamicSharedMemorySize, SMEM_DYN);

    const int GG = (NN + 63) / 64;                 // 782 per half
    const int E2 = (2 * EE + 255) / 256;
    const int N2 = (2 * NN + 255) / 256;
    const int WB2 = (2 * NN * 32 + 255) / 256;

    __half* wfc1 = wh;
    __half* wfc2 = wh + 512 * 128;
    __half* wg1  = wh + 640 * 128;
    __half* wg2  = wh + 896 * 128;
    __half* wfcc = wh + 1024 * 128;

    detect_kernel<<<1, 32>>>((const unsigned int*)ei_a);
    conv_w_all<<<(49152 + 255) / 256, 256>>>(fc1_W, fc2_W, gcn1_W, gcn2_W, fcc_W);

    // CSR build, both graphs
    zero_cnt_kernel<<<N2, 256>>>();
    degree_kernel<<<E2, 256>>>(ei_a, ei_b);
    scan1_kernel<<<2 * CSB, 256>>>();
    scan2_kernel<<<1, 64>>>();
    scan3_kernel<<<N2, 256>>>();
    scatter_kernel<<<E2, 256>>>(ei_a, ei_b);

    // MLP branches (dual) -> cat[:, 0:128] / [:, 128:256]
    mma_gemm<1, 0><<<2 * GG, 256, SMEM_DYN>>>(metadata_a, metadata_b, 512, wfc1, fc1_b,
        p_t2, p_t2 + (size_t)NN * 128, 128, nullptr, nullptr, nullptr, nullptr, nullptr, NN, 512, GG);
    mma_gemm<1, 0><<<2 * GG, 256, SMEM_DYN>>>(p_t2, p_t2 + (size_t)NN * 128, 128, wfc2, fc2_b,
        p_cat + 0, p_cat + 128, 512, nullptr, nullptr, nullptr, nullptr, nullptr, NN, 128, GG);

    // GCN layer 1 (dual): XW -> h16, aggregate -> t2
    mma_gemm<0, 1><<<2 * GG, 256, SMEM_DYN>>>(x_a, x_b, 256, wg1, nullptr,
        nullptr, nullptr, 0, p_h16, p_h16 + (size_t)NN * 128, nullptr, nullptr, nullptr, NN, 256, GG);
    aggregate_kernel<<<WB2, 256>>>(p_h16, gcn1_b, p_t2, 128, (long long)NN * 128);

    // GCN layer 2 (dual): XW -> h16, aggregate -> cat[:, 256:384] / [:, 384:512]
    mma_gemm<0, 1><<<2 * GG, 256, SMEM_DYN>>>(p_t2, p_t2 + (size_t)NN * 128, 128, wg2, nullptr,
        nullptr, nullptr, 0, p_h16, p_h16 + (size_t)NN * 128, nullptr, nullptr, nullptr, NN, 128, GG);
    aggregate_kernel<<<WB2, 256>>>(p_h16, gcn2_b, p_cat + 256, 512, 128LL);

    // fused: out = sigmoid(relu(cat @ fccW + fccb) @ outW + outb)
    mma_gemm<1, 2><<<GG, 256, SMEM_DYN>>>(p_cat, p_cat, 512, wfcc, fcc_b,
        nullptr, nullptr, 0, nullptr, nullptr, out_W, out_b, out, NN, 512, GG);
}

// round 11
// speedup vs baseline: 2.1805x; 1.1159x over previous
#include <cuda_runtime.h>
#include <cuda_bf16.h>
#include <cuda_fp16.h>
#include <cstdint>

#define NN 50000
#define EE 1600000
#define CSB 196              // scan blocks per graph: 196*256 >= 50000

// ---------------- device scratch (no allocs allowed) ----------------
__device__ __align__(256) float  g_cat[NN * 512];        // [ma | mb | ga | gb], ld=512
__device__ __align__(256) __half g_h16[2 * NN * 128];    // GCN features, both graphs
__device__ __align__(256) float  g_t2[2 * NN * 128];     // fc1 out / agg1 out, both
__device__ __align__(256) __half g_wh[1536 * 128];       // fp16 weight planes
__device__ int   g_cnt[2 * NN];
__device__ float g_dinv[2 * NN];
__device__ int   g_rowptr[2 * (NN + 1)];
__device__ int   g_cur[2 * NN];
__device__ int   g_srcidx[2 * EE];
__device__ int   g_bsum[2 * CSB];
__device__ int   g_boff[2 * CSB];
__device__ int   g_is64;

// ---------------- helpers ----------------
__device__ __forceinline__ uint32_t smem_to_u32(const void* p) {
    uint32_t a;
    asm("{ .reg .u64 t; cvta.to.shared.u64 t, %1; cvt.u32.u64 %0, t; }" : "=r"(a) : "l"(p));
    return a;
}
__device__ __forceinline__ void cpa16(uint32_t d, const void* s) {
    asm volatile("cp.async.cg.shared.global [%0], [%1], 16;" :: "r"(d), "l"(s) : "memory");
}
#define CP_COMMIT() asm volatile("cp.async.commit_group;" ::: "memory")
#define CP_WAIT1()  asm volatile("cp.async.wait_group 1;" ::: "memory")
#define CP_WAIT0()  asm volatile("cp.async.wait_group 0;" ::: "memory")

__device__ __forceinline__ unsigned long long pack4h(float4 v) {
    union { unsigned long long u; __half2 h[2]; } P;
    P.h[0] = __floats2half2_rn(v.x, v.y);
    P.h[1] = __floats2half2_rn(v.z, v.w);
    return P.u;
}

#define LDSM_X4(d, a) \
    asm volatile("ldmatrix.sync.aligned.m8n8.x4.shared.b16 {%0,%1,%2,%3}, [%4];" \
        : "=r"((d)[0]), "=r"((d)[1]), "=r"((d)[2]), "=r"((d)[3]) : "r"(a))
#define LDSM_X4_T(d, a) \
    asm volatile("ldmatrix.sync.aligned.m8n8.x4.trans.shared.b16 {%0,%1,%2,%3}, [%4];" \
        : "=r"((d)[0]), "=r"((d)[1]), "=r"((d)[2]), "=r"((d)[3]) : "r"(a))
#define MMA_F16(c, a, b0, b1) \
    asm volatile("mma.sync.aligned.m16n8k16.row.col.f32.f16.f16.f32 " \
        "{%0,%1,%2,%3}, {%4,%5,%6,%7}, {%8,%9}, {%0,%1,%2,%3};" \
        : "+f"((c)[0]), "+f"((c)[1]), "+f"((c)[2]), "+f"((c)[3]) \
        : "r"((a)[0]), "r"((a)[1]), "r"((a)[2]), "r"((a)[3]), "r"(b0), "r"(b1))

// per buffer: A 128x(32+8pad)fp16 = 10240B | B 32x(128+8)fp16 = 8704B
#define BUFS   18944
#define OFF_B  10240
#define SMEM_DYN (2 * BUFS)

// ---------------- HMMA fp16 GEMM (BM=128, warp tile 64x32), dual-input ----------------
// OUTF: 0 = f32 (Cf0/Cf1, ldc), 1 = fp16 (Ch0/Ch1, ld=128), 2 = fused final sigmoid -> outp
template <int ACT, int OUTF>
__global__ __launch_bounds__(256, 2) void mma_gemm(
    const float* __restrict__ A0, const float* __restrict__ A1, int lda,
    const __half* __restrict__ Wh,
    const float* __restrict__ bias,
    float* __restrict__ Cf0, float* __restrict__ Cf1, int ldc,
    __half* __restrict__ Ch0, __half* __restrict__ Ch1,
    const float* __restrict__ outW, const float* __restrict__ outb,
    float* __restrict__ outp,
    int M, int K, int halfGrid)
{
    extern __shared__ char smem[];
    const uint32_t sb = smem_to_u32(smem);
    const int tid = threadIdx.x, wid = tid >> 5, lane = tid & 31;
    const int sel = (blockIdx.x >= halfGrid) ? 1 : 0;
    const float* __restrict__ A = sel ? A1 : A0;
    const int m0 = (blockIdx.x - sel * halfGrid) * 128;
    const int m_off = (wid & 1) * 64, n_off = (wid >> 1) * 32;

    const int mi = lane >> 3, r8 = lane & 7;
    const int aRowL = m_off + (mi & 1) * 8 + r8;    // + mt*16
    const int aColL = (mi >> 1) * 8;                // + k16*16
    const int bRowL = (mi & 1) * 8 + r8;            // + k16*16
    const int bColL = n_off + (mi >> 1) * 8;        // + nt*16

    // A global load mapping: 128 rows x 32 f32 = 1024 float4, 4/thread
    int aRow[4], aK[4];
#pragma unroll
    for (int i = 0; i < 4; i++) {
        const int f = tid + i * 256;
        aRow[i] = f >> 3; aK[i] = (f & 7) * 4;
    }

    float acc[4][4][4];
#pragma unroll
    for (int mt = 0; mt < 4; mt++)
#pragma unroll
        for (int nt = 0; nt < 4; nt++)
#pragma unroll
            for (int j = 0; j < 4; j++) acc[mt][nt][j] = 0.f;

    float4 ra[4];
    const int nch = K >> 5;

    auto gloadA = [&](int c) {
#pragma unroll
        for (int i = 0; i < 4; i++) {
            ra[i] = make_float4(0.f, 0.f, 0.f, 0.f);
            if (m0 + aRow[i] < M)
                ra[i] = *(const float4*)(A + (size_t)(m0 + aRow[i]) * lda + c * 32 + aK[i]);
        }
    };
    auto issueB = [&](int c, int slot) {
        const uint32_t base = sb + slot * BUFS + OFF_B;
#pragma unroll
        for (int i = 0; i < 2; i++) {
            const int f = tid + i * 256;
            const int br = f >> 4, bq = f & 15;
            cpa16(base + br * 272 + bq * 16, Wh + (size_t)(c * 32 + br) * 128 + bq * 8);
        }
    };
    auto sstoreA = [&](int b) {
        char* base = smem + b * BUFS;
#pragma unroll
        for (int i = 0; i < 4; i++)
            *(unsigned long long*)(base + aRow[i] * 80 + aK[i] * 2) = pack4h(ra[i]);
    };
    auto compute = [&](int b) {
        const uint32_t aB = sb + b * BUFS;
        const uint32_t bB = aB + OFF_B;
#pragma unroll
        for (int k16 = 0; k16 < 2; k16++) {
            uint32_t ah[4][4], bh[2][4];
#pragma unroll
            for (int mt = 0; mt < 4; mt++)
                LDSM_X4(ah[mt], aB + (uint32_t)(((aRowL + mt * 16) * 40 + aColL + k16 * 16) * 2));
#pragma unroll
            for (int nt = 0; nt < 2; nt++)
                LDSM_X4_T(bh[nt], bB + (uint32_t)(((bRowL + k16 * 16) * 136 + bColL + nt * 16) * 2));
#pragma unroll
            for (int mt = 0; mt < 4; mt++)
#pragma unroll
                for (int nt = 0; nt < 2; nt++) {
                    MMA_F16(acc[mt][nt * 2 + 0], ah[mt], bh[nt][0], bh[nt][1]);
                    MMA_F16(acc[mt][nt * 2 + 1], ah[mt], bh[nt][2], bh[nt][3]);
                }
        }
    };

    gloadA(0);
    issueB(0, 0); CP_COMMIT();
    sstoreA(0);
    for (int c = 0; c < nch; c++) {
        if (c + 1 < nch) {
            gloadA(c + 1);
            issueB(c + 1, (c + 1) & 1); CP_COMMIT();
            CP_WAIT1();
        } else {
            CP_WAIT0();
        }
        __syncthreads();
        compute(c & 1);
        if (c + 1 < nch) {
            __syncthreads();
            sstoreA((c + 1) & 1);
        }
    }

    // ---------------- epilogue ----------------
    const int er = lane >> 2, ec = (lane & 3) * 2;
    if (OUTF == 2) {
        float* red = (float*)smem;
        __syncthreads();
        if (tid < 128) red[tid] = 0.f;
        __syncthreads();
#pragma unroll
        for (int mt = 0; mt < 4; mt++) {
            float s0 = 0.f, s1 = 0.f;
#pragma unroll
            for (int nt = 0; nt < 4; nt++) {
                const int col = n_off + nt * 8 + ec;
                const float b0 = __ldg(&bias[col]), b1 = __ldg(&bias[col + 1]);
                const float w0 = __ldg(&outW[col]), w1 = __ldg(&outW[col + 1]);
                s0 += fmaxf(acc[mt][nt][0] + b0, 0.f) * w0 + fmaxf(acc[mt][nt][1] + b1, 0.f) * w1;
                s1 += fmaxf(acc[mt][nt][2] + b0, 0.f) * w0 + fmaxf(acc[mt][nt][3] + b1, 0.f) * w1;
            }
            atomicAdd(&red[m_off + mt * 16 + er], s0);
            atomicAdd(&red[m_off + mt * 16 + er + 8], s1);
        }
        __syncthreads();
        if (tid < 128 && m0 + tid < M)
            outp[m0 + tid] = 1.0f / (1.0f + expf(-(red[tid] + __ldg(outb))));
        return;
    }
#pragma unroll
    for (int mt = 0; mt < 4; mt++) {
        const int row0 = m0 + m_off + mt * 16 + er;
#pragma unroll
        for (int nt = 0; nt < 4; nt++) {
            const int col = n_off + nt * 8 + ec;
            float b0 = 0.f, b1 = 0.f;
            if (bias) { b0 = __ldg(&bias[col]); b1 = __ldg(&bias[col + 1]); }
            float v0 = acc[mt][nt][0] + b0, v1 = acc[mt][nt][1] + b1;
            float v2 = acc[mt][nt][2] + b0, v3 = acc[mt][nt][3] + b1;
            if (ACT) {
                v0 = fmaxf(v0, 0.f); v1 = fmaxf(v1, 0.f);
                v2 = fmaxf(v2, 0.f); v3 = fmaxf(v3, 0.f);
            }
            if (OUTF == 0) {
                float* Cf = sel ? Cf1 : Cf0;
                if (row0 < M) *(float2*)(Cf + (size_t)row0 * ldc + col) = make_float2(v0, v1);
                if (row0 + 8 < M) *(float2*)(Cf + (size_t)(row0 + 8) * ldc + col) = make_float2(v2, v3);
            } else {
                __half* Ch = sel ? Ch1 : Ch0;
                if (row0 < M)
                    *(__half2*)(Ch + (size_t)row0 * 128 + col) = __floats2half2_rn(v0, v1);
                if (row0 + 8 < M)
                    *(__half2*)(Ch + (size_t)(row0 + 8) * 128 + col) = __floats2half2_rn(v2, v3);
            }
        }
    }
}

// ---------------- merged weight conversion (f32 -> fp16 plane) ----------------
__global__ void conv_w_all(const float* __restrict__ w0, const float* __restrict__ w1,
                           const float* __restrict__ w2, const float* __restrict__ w3,
                           const float* __restrict__ w4)
{
    const int i = blockIdx.x * blockDim.x + threadIdx.x;   // float4 index, 49152 total
    if (i >= 49152) return;
    const float* src; int rel, dst;
    if (i < 16384)      { src = w0; rel = i;         dst = 0;         }
    else if (i < 20480) { src = w1; rel = i - 16384; dst = 512 * 32;  }
    else if (i < 28672) { src = w2; rel = i - 20480; dst = 640 * 32;  }
    else if (i < 32768) { src = w3; rel = i - 28672; dst = 896 * 32;  }
    else                { src = w4; rel = i - 32768; dst = 1024 * 32; }
    ((unsigned long long*)g_wh)[dst + rel] = pack4h(((const float4*)src)[rel]);
}

// ---------------- edge-index dtype detection ----------------
__global__ void detect_kernel(const unsigned int* __restrict__ w) {
    if (threadIdx.x == 0 && blockIdx.x == 0) {
        int zeros = 0;
        for (int i = 1; i < 512; i += 2) zeros += (w[i] == 0u) ? 1 : 0;
        g_is64 = (zeros >= 200) ? 1 : 0;
    }
}
__device__ __forceinline__ int load_idx(const void* ei, long long pos, int is64) {
    if (is64) return (int)((const long long*)ei)[pos];
    return ((const int*)ei)[pos];
}

// ---------------- CSR build (both graphs per launch) ----------------
__global__ void zero_cnt_kernel() {
    const int i = blockIdx.x * blockDim.x + threadIdx.x;
    if (i < 2 * NN) g_cnt[i] = 0;
}
__global__ void degree_kernel(const void* __restrict__ eia, const void* __restrict__ eib) {
    const int i = blockIdx.x * blockDim.x + threadIdx.x;
    if (i < 2 * EE) {
        const int g = (i >= EE) ? 1 : 0;
        const void* ei = g ? eib : eia;
        const int e = i - g * EE;
        const int dst = load_idx(ei, (long long)EE + e, g_is64);
        if ((unsigned)dst < NN) atomicAdd(&g_cnt[g * NN + dst], 1);
    }
}
__global__ void scan1_kernel() {
    __shared__ int wsum[8];
    const int g = (blockIdx.x >= CSB) ? 1 : 0;
    const int b = blockIdx.x - g * CSB;
    const int t = threadIdx.x, lane = t & 31, wd = t >> 5;
    const int idx = b * 256 + t;
    const int v = (idx < NN) ? g_cnt[g * NN + idx] : 0;
    int x = v;
#pragma unroll
    for (int off = 1; off < 32; off <<= 1) {
        const int y = __shfl_up_sync(0xffffffffu, x, off);
        if (lane >= off) x += y;
    }
    if (lane == 31) wsum[wd] = x;
    __syncthreads();
    if (t < 8) {
        int s = wsum[t];
#pragma unroll
        for (int off = 1; off < 8; off <<= 1) {
            const int y = __shfl_up_sync(0xffu, s, off);
            if (t >= off) s += y;
        }
        wsum[t] = s;
    }
    __syncthreads();
    const int excl = (wd ? wsum[wd - 1] : 0) + x - v;
    if (idx < NN) g_rowptr[g * (NN + 1) + idx] = excl;
    if (t == 255) g_bsum[g * CSB + b] = excl + v;
}
__global__ void scan2_kernel() {
    const int t = threadIdx.x, lane = t & 31, g = t >> 5;
    if (g >= 2) return;
    int carry = 0;
    for (int base = 0; base < CSB; base += 32) {
        const int i = base + lane;
        const int v = (i < CSB) ? g_bsum[g * CSB + i] : 0;
        int x = v;
#pragma unroll
        for (int off = 1; off < 32; off <<= 1) {
            const int y = __shfl_up_sync(0xffffffffu, x, off);
            if (lane >= off) x += y;
        }
        if (i < CSB) g_boff[g * CSB + i] = carry + x - v;
        carry += __shfl_sync(0xffffffffu, x, 31);
    }
    if (lane == 0) g_rowptr[g * (NN + 1) + NN] = carry;
}
__global__ void scan3_kernel() {
    const int i = blockIdx.x * blockDim.x + threadIdx.x;
    if (i >= 2 * NN) return;
    const int g = (i >= NN) ? 1 : 0;
    const int ln = i - g * NN;
    const int rp = g_rowptr[g * (NN + 1) + ln] + g_boff[g * CSB + ln / 256];
    g_rowptr[g * (NN + 1) + ln] = rp;
    g_cur[i] = rp;
    g_dinv[i] = rsqrtf((float)g_cnt[i] + 1.0f);
}
__global__ void scatter_kernel(const void* __restrict__ eia, const void* __restrict__ eib) {
    const int i = blockIdx.x * blockDim.x + threadIdx.x;
    if (i < 2 * EE) {
        const int g = (i >= EE) ? 1 : 0;
        const void* ei = g ? eib : eia;
        const int e = i - g * EE;
        const int is64 = g_is64;
        const int dst = load_idx(ei, (long long)EE + e, is64);
        const int src = load_idx(ei, (long long)e, is64);
        if ((unsigned)dst < NN && (unsigned)src < NN) {
            const int pos = atomicAdd(&g_cur[g * NN + dst], 1);
            if ((unsigned)pos < EE) g_srcidx[(size_t)g * EE + pos] = src;
        }
    }
}

// ---------------- GCN aggregation, both graphs: fp16 gather, f32 out ----------------
__global__ __launch_bounds__(256) void aggregate_kernel(
    const __half* __restrict__ H, const float* __restrict__ bias,
    float* __restrict__ out, int ldo, long long goff)
{
    const int gt = blockIdx.x * blockDim.x + threadIdx.x;
    const int node = gt >> 5, lane = gt & 31;
    if (node >= 2 * NN) return;
    const int g = (node >= NN) ? 1 : 0;
    const int ln = node - g * NN;
    const int* __restrict__ rp = g_rowptr + g * (NN + 1);
    const float* __restrict__ dv = g_dinv + g * NN;
    const int* __restrict__ si = g_srcidx + (size_t)g * EE;
    const __half* __restrict__ Hg = H + (size_t)g * NN * 128;

    const float di = dv[ln];
    float acc[4];
    {
        const float w = di * di;
        const uint2 v = *(const uint2*)(Hg + (size_t)ln * 128 + lane * 4);
        const float2 f0 = __half22float2(*(const __half2*)&v.x);
        const float2 f1 = __half22float2(*(const __half2*)&v.y);
        acc[0] = f0.x * w; acc[1] = f0.y * w; acc[2] = f1.x * w; acc[3] = f1.y * w;
    }
    const int beg = rp[ln], end = rp[ln + 1];
    for (int e = beg; e < end; e++) {
        const int s = __ldg(&si[e]);
        const float w = di * __ldg(&dv[s]);
        const uint2 v = *(const uint2*)(Hg + (size_t)s * 128 + lane * 4);
        const float2 f0 = __half22float2(*(const __half2*)&v.x);
        const float2 f1 = __half22float2(*(const __half2*)&v.y);
        acc[0] = fmaf(f0.x, w, acc[0]);
        acc[1] = fmaf(f0.y, w, acc[1]);
        acc[2] = fmaf(f1.x, w, acc[2]);
        acc[3] = fmaf(f1.y, w, acc[3]);
    }
    const float4 b = *(const float4*)(bias + lane * 4);
    *(float4*)(out + (size_t)g * goff + (size_t)ln * ldo + lane * 4) =
        make_float4(fmaxf(acc[0] + b.x, 0.f), fmaxf(acc[1] + b.y, 0.f),
                    fmaxf(acc[2] + b.z, 0.f), fmaxf(acc[3] + b.w, 0.f));
}

// ---------------- orchestration ----------------
extern "C" void kernel_launch(void* const* d_in, const int* in_sizes, int n_in,
                              void* d_out, int out_size)
{
    const float* metadata_a = (const float*)d_in[0];
    const float* metadata_b = (const float*)d_in[1];
    const float* x_a        = (const float*)d_in[2];
    const float* x_b        = (const float*)d_in[3];
    const void*  ei_a       = d_in[4];
    const void*  ei_b       = d_in[5];
    const float* fc1_W  = (const float*)d_in[6];
    const float* fc1_b  = (const float*)d_in[7];
    const float* fc2_W  = (const float*)d_in[8];
    const float* fc2_b  = (const float*)d_in[9];
    const float* gcn1_W = (const float*)d_in[10];
    const float* gcn1_b = (const float*)d_in[11];
    const float* gcn2_W = (const float*)d_in[12];
    const float* gcn2_b = (const float*)d_in[13];
    const float* fcc_W  = (const float*)d_in[14];
    const float* fcc_b  = (const float*)d_in[15];
    const float* out_W  = (const float*)d_in[16];
    const float* out_b  = (const float*)d_in[17];
    float* out = (float*)d_out;

    float *p_cat, *p_t2;
    __half *p_h16, *wh;
    cudaGetSymbolAddress((void**)&p_cat, g_cat);
    cudaGetSymbolAddress((void**)&p_t2, g_t2);
    cudaGetSymbolAddress((void**)&p_h16, g_h16);
    cudaGetSymbolAddress((void**)&wh, g_wh);

    cudaFuncSetAttribute(mma_gemm<1, 0>, cudaFuncAttributeMaxDynamicSharedMemorySize, SMEM_DYN);
    cudaFuncSetAttribute(mma_gemm<0, 1>, cudaFuncAttributeMaxDynamicSharedMemorySize, SMEM_DYN);
    cudaFuncSetAttribute(mma_gemm<1, 2>, cudaFuncAttributeMaxDynamicSharedMemorySize, SMEM_DYN);

    const int GG = (NN + 127) / 128;               // 391 per half
    const int E2 = (2 * EE + 255) / 256;
    const int N2 = (2 * NN + 255) / 256;
    const int WB2 = (2 * NN * 32 + 255) / 256;

    __half* wfc1 = wh;
    __half* wfc2 = wh + 512 * 128;
    __half* wg1  = wh + 640 * 128;
    __half* wg2  = wh + 896 * 128;
    __half* wfcc = wh + 1024 * 128;

    detect_kernel<<<1, 32>>>((const unsigned int*)ei_a);
    conv_w_all<<<(49152 + 255) / 256, 256>>>(fc1_W, fc2_W, gcn1_W, gcn2_W, fcc_W);

    // CSR build, both graphs
    zero_cnt_kernel<<<N2, 256>>>();
    degree_kernel<<<E2, 256>>>(ei_a, ei_b);
    scan1_kernel<<<2 * CSB, 256>>>();
    scan2_kernel<<<1, 64>>>();
    scan3_kernel<<<N2, 256>>>();
    scatter_kernel<<<E2, 256>>>(ei_a, ei_b);

    // MLP branches (dual) -> cat[:, 0:128] / [:, 128:256]
    mma_gemm<1, 0><<<2 * GG, 256, SMEM_DYN>>>(metadata_a, metadata_b, 512, wfc1, fc1_b,
        p_t2, p_t2 + (size_t)NN * 128, 128, nullptr, nullptr, nullptr, nullptr, nullptr, NN, 512, GG);
    mma_gemm<1, 0><<<2 * GG, 256, SMEM_DYN>>>(p_t2, p_t2 + (size_t)NN * 128, 128, wfc2, fc2_b,
        p_cat + 0, p_cat + 128, 512, nullptr, nullptr, nullptr, nullptr, nullptr, NN, 128, GG);

    // GCN layer 1 (dual): XW -> h16, aggregate -> t2
    mma_gemm<0, 1><<<2 * GG, 256, SMEM_DYN>>>(x_a, x_b, 256, wg1, nullptr,
        nullptr, nullptr, 0, p_h16, p_h16 + (size_t)NN * 128, nullptr, nullptr, nullptr, NN, 256, GG);
    aggregate_kernel<<<WB2, 256>>>(p_h16, gcn1_b, p_t2, 128, (long long)NN * 128);

    // GCN layer 2 (dual): XW -> h16, aggregate -> cat[:, 256:384] / [:, 384:512]
    mma_gemm<0, 1><<<2 * GG, 256, SMEM_DYN>>>(p_t2, p_t2 + (size_t)NN * 128, 128, wg2, nullptr,
        nullptr, nullptr, 0, p_h16, p_h16 + (size_t)NN * 128, nullptr, nullptr, nullptr, NN, 128, GG);
    aggregate_kernel<<<WB2, 256>>>(p_h16, gcn2_b, p_cat + 256, 512, 128LL);

    // fused: out = sigmoid(relu(cat @ fccW + fccb) @ outW + outb)
    mma_gemm<1, 2><<<GG, 256, SMEM_DYN>>>(p_cat, p_cat, 512, wfcc, fcc_b,
        nullptr, nullptr, 0, nullptr, nullptr, out_W, out_b, out, NN, 512, GG);
}